// round 6
// baseline (speedup 1.0000x reference)
#include <cuda_runtime.h>
#include <cuda_fp16.h>
#include <cuda_bf16.h>
#include <cstdint>

#define NNODES 8192
#define NEDGES 262144
#define DIN    512
#define DH     256
#define ALPHA  0.1520f
#define BETA   0.7900f

// ---------------- scratch (device globals; no allocation allowed) ----------
__device__ float  g_deg [NNODES];
__device__ float  g_dinv[NNODES];
__device__ __nv_bfloat16 g_Xh [NNODES * DIN];
__device__ __nv_bfloat16 g_Xl [NNODES * DIN];
__device__ __nv_bfloat16 g_W1h[DIN * DH];
__device__ __nv_bfloat16 g_W1l[DIN * DH];
__device__ float  g_Y1  [NNODES * DH];   // X @ W1 (fp32)
__device__ __half g_Y1h [NNODES * DH];   // fp16 copy for prop1 gather
__device__ float  g_P1  [NNODES * DH];   // edge-aggregated Y1 (atomic target)
__device__ float  g_Y2  [NNODES * 2];
__device__ float  g_eacc[NNODES * 2];
__device__ float  g_ex  [NNODES];
__device__ float  g_ey  [NNODES];

// ---------------- zero accumulators (must run every replay) ----------------
__global__ void zero_kernel() {
    int idx = blockIdx.x * blockDim.x + threadIdx.x;
    float4 z = make_float4(0.f, 0.f, 0.f, 0.f);
    if (idx < NNODES * DH / 4) ((float4*)g_P1)[idx] = z;
    if (idx < NNODES * 2 / 4)  ((float4*)g_eacc)[idx] = z;
    if (idx < NNODES / 4)      ((float4*)g_deg)[idx] = z;
}

__global__ void deg_kernel(const int* __restrict__ dst) {
    int e = blockIdx.x * blockDim.x + threadIdx.x;
    if (e < NEDGES) atomicAdd(&g_deg[dst[e]], 1.0f);
}

__global__ void dinv_kernel() {
    int i = blockIdx.x * blockDim.x + threadIdx.x;
    if (i < NNODES) g_dinv[i] = rsqrtf(g_deg[i] + 1.0f);
}

// ---------------- bf16 split pre-pass --------------------------------------
__device__ __forceinline__ void split4(float4 v, uint2* ph, uint2* pl) {
    __nv_bfloat16 h0 = __float2bfloat16_rn(v.x);
    __nv_bfloat16 h1 = __float2bfloat16_rn(v.y);
    __nv_bfloat16 h2 = __float2bfloat16_rn(v.z);
    __nv_bfloat16 h3 = __float2bfloat16_rn(v.w);
    __nv_bfloat16 l0 = __float2bfloat16_rn(v.x - __bfloat162float(h0));
    __nv_bfloat16 l1 = __float2bfloat16_rn(v.y - __bfloat162float(h1));
    __nv_bfloat16 l2 = __float2bfloat16_rn(v.z - __bfloat162float(h2));
    __nv_bfloat16 l3 = __float2bfloat16_rn(v.w - __bfloat162float(h3));
    ph->x = ((uint32_t)__bfloat16_as_ushort(h1) << 16) | __bfloat16_as_ushort(h0);
    ph->y = ((uint32_t)__bfloat16_as_ushort(h3) << 16) | __bfloat16_as_ushort(h2);
    pl->x = ((uint32_t)__bfloat16_as_ushort(l1) << 16) | __bfloat16_as_ushort(l0);
    pl->y = ((uint32_t)__bfloat16_as_ushort(l3) << 16) | __bfloat16_as_ushort(l2);
}

__global__ void splitX_kernel(const float* __restrict__ X) {
    int i = blockIdx.x * blockDim.x + threadIdx.x;
    if (i >= NNODES * DIN / 4) return;
    float4 v = __ldg(&((const float4*)X)[i]);
    uint2 ph, pl;
    split4(v, &ph, &pl);
    ((uint2*)g_Xh)[i] = ph;
    ((uint2*)g_Xl)[i] = pl;
}

__global__ void splitW_kernel(const float* __restrict__ W1) {
    int i = blockIdx.x * blockDim.x + threadIdx.x;
    if (i >= DIN * DH / 4) return;
    float4 v = __ldg(&((const float4*)W1)[i]);
    uint2 ph, pl;
    split4(v, &ph, &pl);
    ((uint2*)g_W1h)[i] = ph;
    ((uint2*)g_W1l)[i] = pl;
}

// ================= GEMM1 via mma.sync bf16 (3-term split) ==================
// CTA tile 128(m) x 64(n); K chunks of 64, double-buffered cp.async.
// Per stage: Ah 16KB | Al 16KB | Bh 8KB | Bl 8KB = 48KB; 2 stages = 96KB.

#define STAGE_BYTES 49152
#define GEMM_SMEM   (2 * STAGE_BYTES)

__device__ __forceinline__ uint32_t smem_u32(const void* p) {
    uint32_t a;
    asm("{ .reg .u64 t; cvta.to.shared.u64 t, %1; cvt.u32.u64 %0, t; }" : "=r"(a) : "l"(p));
    return a;
}
__device__ __forceinline__ void cp16(uint32_t dst, const void* src) {
    asm volatile("cp.async.ca.shared.global [%0], [%1], 16;" :: "r"(dst), "l"(src));
}
__device__ __forceinline__ void ldmatrix_x4(uint32_t* r, uint32_t addr) {
    asm volatile("ldmatrix.sync.aligned.m8n8.x4.shared.b16 {%0,%1,%2,%3}, [%4];"
                 : "=r"(r[0]), "=r"(r[1]), "=r"(r[2]), "=r"(r[3]) : "r"(addr));
}
__device__ __forceinline__ void ldmatrix_x2t(uint32_t* r, uint32_t addr) {
    asm volatile("ldmatrix.sync.aligned.m8n8.x2.trans.shared.b16 {%0,%1}, [%2];"
                 : "=r"(r[0]), "=r"(r[1]) : "r"(addr));
}
__device__ __forceinline__ void mma_bf16(float* d, const uint32_t* a, const uint32_t* b) {
    asm volatile(
        "mma.sync.aligned.m16n8k16.row.col.f32.bf16.bf16.f32 "
        "{%0,%1,%2,%3}, {%4,%5,%6,%7}, {%8,%9}, {%0,%1,%2,%3};"
        : "+f"(d[0]), "+f"(d[1]), "+f"(d[2]), "+f"(d[3])
        : "r"(a[0]), "r"(a[1]), "r"(a[2]), "r"(a[3]), "r"(b[0]), "r"(b[1]));
}

__device__ __forceinline__ void gemm_prefetch(uint32_t sb, int tid, int bm, int bn, int k0) {
#pragma unroll
    for (int p = 0; p < 4; ++p) {
        int idx = tid + p * 256;
        int row = idx >> 3, c16 = idx & 7;
        uint32_t off = (uint32_t)(row * 128 + c16 * 16);
        off ^= (uint32_t)(row & 7) << 4;
        const __nv_bfloat16* sh = g_Xh + (size_t)(bm + row) * DIN + k0 + c16 * 8;
        const __nv_bfloat16* sl = g_Xl + (size_t)(bm + row) * DIN + k0 + c16 * 8;
        cp16(sb + off, sh);
        cp16(sb + 16384 + off, sl);
    }
#pragma unroll
    for (int p = 0; p < 2; ++p) {
        int idx = tid + p * 256;
        int row = idx >> 3, c16 = idx & 7;
        uint32_t off = (uint32_t)(row * 128 + c16 * 16);
        off ^= (uint32_t)(row & 7) << 4;
        cp16(sb + 32768 + off, g_W1h + (size_t)(k0 + row) * DH + bn + c16 * 8);
        cp16(sb + 40960 + off, g_W1l + (size_t)(k0 + row) * DH + bn + c16 * 8);
    }
    asm volatile("cp.async.commit_group;");
}

__global__ __launch_bounds__(256) void gemm1_mma_kernel() {
    extern __shared__ __align__(1024) char sm[];
    const uint32_t sbase = smem_u32(sm);
    const int tid = threadIdx.x;
    const int wid = tid >> 5, lane = tid & 31;
    const int bm = blockIdx.y * 128;
    const int bn = blockIdx.x * 64;
    const int wm0 = (wid & 3) * 32;
    const int wn0 = (wid >> 2) * 32;

    float d[2][4][4];
#pragma unroll
    for (int mt = 0; mt < 2; ++mt)
#pragma unroll
        for (int nt = 0; nt < 4; ++nt)
#pragma unroll
            for (int u = 0; u < 4; ++u) d[mt][nt][u] = 0.f;

    gemm_prefetch(sbase, tid, bm, bn, 0);

    for (int ch = 0; ch < 8; ++ch) {
        const uint32_t stb = sbase + (uint32_t)(ch & 1) * STAGE_BYTES;
        if (ch < 7) {
            gemm_prefetch(sbase + (uint32_t)((ch + 1) & 1) * STAGE_BYTES, tid, bm, bn, (ch + 1) * 64);
            asm volatile("cp.async.wait_group 1;");
        } else {
            asm volatile("cp.async.wait_group 0;");
        }
        __syncthreads();

#pragma unroll
        for (int ks = 0; ks < 4; ++ks) {
            const int kk = ks * 16;
            uint32_t ah[2][4], al[2][4], bh[4][2], bl[4][2];
#pragma unroll
            for (int mt = 0; mt < 2; ++mt) {
                int row = wm0 + mt * 16 + (lane & 15);
                uint32_t off = (uint32_t)(row * 128 + kk * 2 + ((lane >> 4) << 4));
                off ^= (uint32_t)(row & 7) << 4;
                ldmatrix_x4(ah[mt], stb + off);
                ldmatrix_x4(al[mt], stb + 16384 + off);
            }
#pragma unroll
            for (int nt = 0; nt < 4; ++nt) {
                int row = kk + (lane & 15);
                uint32_t off = (uint32_t)(row * 128 + (wn0 + nt * 8) * 2);
                off ^= (uint32_t)(row & 7) << 4;
                ldmatrix_x2t(bh[nt], stb + 32768 + off);
                ldmatrix_x2t(bl[nt], stb + 40960 + off);
            }
#pragma unroll
            for (int mt = 0; mt < 2; ++mt)
#pragma unroll
                for (int nt = 0; nt < 4; ++nt) {
                    mma_bf16(d[mt][nt], ah[mt], bh[nt]);
                    mma_bf16(d[mt][nt], ah[mt], bl[nt]);
                    mma_bf16(d[mt][nt], al[mt], bh[nt]);
                }
        }
        __syncthreads();
    }

    // ---- epilogue: write fp32 Y1 + fp16 copy ----
    const int group = lane >> 2, tig = lane & 3;
#pragma unroll
    for (int mt = 0; mt < 2; ++mt) {
#pragma unroll
        for (int nt = 0; nt < 4; ++nt) {
            int row = bm + wm0 + mt * 16 + group;
            int col = bn + wn0 + nt * 8 + tig * 2;
            float2 v01 = make_float2(d[mt][nt][0], d[mt][nt][1]);
            float2 v23 = make_float2(d[mt][nt][2], d[mt][nt][3]);
            *(float2*)&g_Y1[(size_t)row * DH + col] = v01;
            *(float2*)&g_Y1[(size_t)(row + 8) * DH + col] = v23;
            __half2 h01 = __floats2half2_rn(v01.x, v01.y);
            __half2 h23 = __floats2half2_rn(v23.x, v23.y);
            *(__half2*)&g_Y1h[(size_t)row * DH + col] = h01;
            *(__half2*)&g_Y1h[(size_t)(row + 8) * DH + col] = h23;
        }
    }
}

// ---------------- prop1: P1[dst] += Y1h[src] * (dinv[src]*dinv[dst]) -------
__global__ __launch_bounds__(256) void prop1_kernel(const int* __restrict__ src,
                                                    const int* __restrict__ dst) {
    int w = (blockIdx.x * blockDim.x + threadIdx.x) >> 5;
    int lane = threadIdx.x & 31;
    if (w >= NEDGES) return;
    int s = __ldg(&src[w]);
    int d = __ldg(&dst[w]);
    float nrm = g_dinv[s] * g_dinv[d];
    const uint4* yrow = (const uint4*)(g_Y1h + (size_t)s * DH);
    float* prow = g_P1 + (size_t)d * DH + (lane << 3);
    uint4 v = __ldg(&yrow[lane]);
    float2 f0 = __half22float2(*(__half2*)&v.x);
    float2 f1 = __half22float2(*(__half2*)&v.y);
    float2 f2 = __half22float2(*(__half2*)&v.z);
    float2 f3 = __half22float2(*(__half2*)&v.w);
    asm volatile("red.global.add.v4.f32 [%0], {%1,%2,%3,%4};"
                 :: "l"(prow), "f"(f0.x * nrm), "f"(f0.y * nrm),
                    "f"(f1.x * nrm), "f"(f1.y * nrm) : "memory");
    asm volatile("red.global.add.v4.f32 [%0], {%1,%2,%3,%4};"
                 :: "l"(prow + 4), "f"(f2.x * nrm), "f"(f2.y * nrm),
                    "f"(f3.x * nrm), "f"(f3.y * nrm) : "memory");
}

// ---------------- node fuse: h = relu(P1 + Y1*dinv^2 + b1); Y2 = h @ W2 ----
__global__ __launch_bounds__(256) void node2_kernel(const float* __restrict__ b1,
                                                    const float* __restrict__ W2) {
    int node = (blockIdx.x * blockDim.x + threadIdx.x) >> 5;
    int lane = threadIdx.x & 31;
    if (node >= NNODES) return;
    float di = g_dinv[node];
    float di2 = di * di;
    const float* prow = g_P1 + (size_t)node * DH;
    const float* yrow = g_Y1 + (size_t)node * DH;
    const float2* w2 = (const float2*)W2;
    float s0 = 0.f, s1 = 0.f;
#pragma unroll
    for (int j = 0; j < DH / 32; ++j) {
        int d = lane + j * 32;
        float h = prow[d] + yrow[d] * di2 + b1[d];
        h = fmaxf(h, 0.f);
        float2 w = __ldg(&w2[d]);
        s0 = fmaf(h, w.x, s0);
        s1 = fmaf(h, w.y, s1);
    }
#pragma unroll
    for (int off = 16; off > 0; off >>= 1) {
        s0 += __shfl_down_sync(0xffffffffu, s0, off);
        s1 += __shfl_down_sync(0xffffffffu, s1, off);
    }
    if (lane == 0) {
        g_Y2[node * 2 + 0] = s0;
        g_Y2[node * 2 + 1] = s1;
    }
}

// ---------------- prop2 ----------------------------------------------------
__global__ void prop2_kernel(const int* __restrict__ src, const int* __restrict__ dst) {
    int e = blockIdx.x * blockDim.x + threadIdx.x;
    if (e >= NEDGES) return;
    int s = src[e], d = dst[e];
    float nrm = g_dinv[s] * g_dinv[d];
    float2 y = ((const float2*)g_Y2)[s];
    float* p = g_eacc + (size_t)d * 2;
    asm volatile("red.global.add.v2.f32 [%0], {%1,%2};"
                 :: "l"(p), "f"(y.x * nrm), "f"(y.y * nrm) : "memory");
}

// ---------------- finalize emb ---------------------------------------------
__global__ void fin_kernel(const float* __restrict__ b2, float* __restrict__ out) {
    int i = blockIdx.x * blockDim.x + threadIdx.x;
    if (i >= NNODES) return;
    float di = g_dinv[i];
    float di2 = di * di;
    float2 y = ((const float2*)g_Y2)[i];
    float ex = g_eacc[2 * i + 0] + y.x * di2 + b2[0];
    float ey = g_eacc[2 * i + 1] + y.y * di2 + b2[1];
    g_ex[i] = ex;
    g_ey[i] = ey;
    out[2 * i + 0] = ex;
    out[2 * i + 1] = ey;
}

// ---------------- q: symmetric upper-triangular 64x64 tiles ----------------
__device__ __forceinline__ float qval(float dx, float dy) {
    float d2 = fmaf(dx, dx, dy * dy);
    float pw = __powf(d2, BETA);
    float q  = __fdividef(1.0f, fmaf(ALPHA, pw, 1.0f));
    return d2 > 0.0f ? q : 1.0f;
}

__global__ __launch_bounds__(256) void q_kernel(float* __restrict__ qout) {
    __shared__ float qs[64][65];
    int b = blockIdx.x;
    int r = (int)((257.0f - sqrtf(66049.0f - 8.0f * (float)b)) * 0.5f);
    while ((r + 1) * 128 - ((r + 1) * r) / 2 <= b) ++r;
    while (r * 128 - (r * (r - 1)) / 2 > b) --r;
    int S = r * 128 - (r * (r - 1)) / 2;
    int bi = r;
    int bj = r + (b - S);
    int ty = threadIdx.x >> 4, tx = threadIdx.x & 15;
    int r0 = ty * 4, c0 = tx * 4;
    bool diag = (bi == bj);

    float4 xj = *(const float4*)&g_ex[bj * 64 + c0];
    float4 yj = *(const float4*)&g_ey[bj * 64 + c0];
#pragma unroll
    for (int u = 0; u < 4; ++u) {
        float xi = g_ex[bi * 64 + r0 + u];
        float yi = g_ey[bi * 64 + r0 + u];
        float4 v;
        v.x = qval(xi - xj.x, yi - yj.x);
        v.y = qval(xi - xj.y, yi - yj.y);
        v.z = qval(xi - xj.z, yi - yj.z);
        v.w = qval(xi - xj.w, yi - yj.w);
        *(float4*)&qout[(size_t)(bi * 64 + r0 + u) * NNODES + bj * 64 + c0] = v;
        if (!diag) {
            qs[r0 + u][c0 + 0] = v.x;
            qs[r0 + u][c0 + 1] = v.y;
            qs[r0 + u][c0 + 2] = v.z;
            qs[r0 + u][c0 + 3] = v.w;
        }
    }
    if (!diag) {
        __syncthreads();
#pragma unroll
        for (int u = 0; u < 4; ++u) {
            float4 v;
            v.x = qs[c0 + 0][r0 + u];
            v.y = qs[c0 + 1][r0 + u];
            v.z = qs[c0 + 2][r0 + u];
            v.w = qs[c0 + 3][r0 + u];
            *(float4*)&qout[(size_t)(bj * 64 + r0 + u) * NNODES + bi * 64 + c0] = v;
        }
    }
}

// ---------------------------------------------------------------------------
extern "C" void kernel_launch(void* const* d_in, const int* in_sizes, int n_in,
                              void* d_out, int out_size) {
    const float* X  = (const float*)d_in[0];
    const int*   ei = (const int*)  d_in[1];
    const float* W1 = (const float*)d_in[2];
    const float* b1 = (const float*)d_in[3];
    const float* W2 = (const float*)d_in[4];
    const float* b2 = (const float*)d_in[5];
    float* out = (float*)d_out;
    (void)in_sizes; (void)n_in; (void)out_size;

    const int* src = ei;
    const int* dst = ei + NEDGES;

    static int smem_set = 0;
    if (!smem_set) {
        cudaFuncSetAttribute(gemm1_mma_kernel,
                             cudaFuncAttributeMaxDynamicSharedMemorySize, GEMM_SMEM);
        smem_set = 1;
    }

    zero_kernel<<<(NNODES * DH / 4 + 255) / 256, 256>>>();
    deg_kernel<<<NEDGES / 256, 256>>>(dst);
    dinv_kernel<<<NNODES / 256, 256>>>();
    splitX_kernel<<<NNODES * DIN / 4 / 256, 256>>>(X);
    splitW_kernel<<<DIN * DH / 4 / 256, 256>>>(W1);
    gemm1_mma_kernel<<<dim3(DH / 64, NNODES / 128), 256, GEMM_SMEM>>>();
    prop1_kernel<<<NEDGES * 32 / 256, 256>>>(src, dst);
    node2_kernel<<<NNODES * 32 / 256, 256>>>(b1, W2);
    prop2_kernel<<<NEDGES / 256, 256>>>(src, dst);
    fin_kernel<<<NNODES / 256, 256>>>(b2, out);
    q_kernel<<<128 * 129 / 2, 256>>>(out + NNODES * 2);
}

// round 7
// speedup vs baseline: 1.1900x; 1.1900x over previous
#include <cuda_runtime.h>
#include <cuda_bf16.h>
#include <cstdint>

#define NNODES 8192
#define NEDGES 262144
#define DIN    512
#define DH     256
#define ALPHA  0.1520f
#define BETA   0.7900f

// ---------------- scratch (device globals; no allocation allowed) ----------
__device__ float  g_deg [NNODES];
__device__ float  g_dinv[NNODES];
__device__ __nv_bfloat16 g_Xh [NNODES * DIN];
__device__ __nv_bfloat16 g_Xl [NNODES * DIN];
__device__ __nv_bfloat16 g_W1h[DIN * DH];
__device__ __nv_bfloat16 g_W1l[DIN * DH];
__device__ float  g_Y1  [NNODES * DH];   // X @ W1 (fp32)
__device__ float  g_P1  [NNODES * DH];   // edge-aggregated Y1 (atomic target)
__device__ float  g_Y2  [NNODES * 2];
__device__ float  g_eacc[NNODES * 2];
__device__ float  g_ex  [NNODES];
__device__ float  g_ey  [NNODES];

// ---------------- zero accumulators (must run every replay) ----------------
__global__ void zero_kernel() {
    int idx = blockIdx.x * blockDim.x + threadIdx.x;
    float4 z = make_float4(0.f, 0.f, 0.f, 0.f);
    if (idx < NNODES * DH / 4) ((float4*)g_P1)[idx] = z;
    if (idx < NNODES * 2 / 4)  ((float4*)g_eacc)[idx] = z;
    if (idx < NNODES / 4)      ((float4*)g_deg)[idx] = z;
}

__global__ void deg_kernel(const int* __restrict__ dst) {
    int e = blockIdx.x * blockDim.x + threadIdx.x;
    if (e < NEDGES) atomicAdd(&g_deg[dst[e]], 1.0f);
}

__global__ void dinv_kernel() {
    int i = blockIdx.x * blockDim.x + threadIdx.x;
    if (i < NNODES) g_dinv[i] = rsqrtf(g_deg[i] + 1.0f);
}

// ---------------- bf16 split pre-pass (X and W1 fused) ---------------------
__device__ __forceinline__ void split4(float4 v, uint2* ph, uint2* pl) {
    __nv_bfloat16 h0 = __float2bfloat16_rn(v.x);
    __nv_bfloat16 h1 = __float2bfloat16_rn(v.y);
    __nv_bfloat16 h2 = __float2bfloat16_rn(v.z);
    __nv_bfloat16 h3 = __float2bfloat16_rn(v.w);
    __nv_bfloat16 l0 = __float2bfloat16_rn(v.x - __bfloat162float(h0));
    __nv_bfloat16 l1 = __float2bfloat16_rn(v.y - __bfloat162float(h1));
    __nv_bfloat16 l2 = __float2bfloat16_rn(v.z - __bfloat162float(h2));
    __nv_bfloat16 l3 = __float2bfloat16_rn(v.w - __bfloat162float(h3));
    ph->x = ((uint32_t)__bfloat16_as_ushort(h1) << 16) | __bfloat16_as_ushort(h0);
    ph->y = ((uint32_t)__bfloat16_as_ushort(h3) << 16) | __bfloat16_as_ushort(h2);
    pl->x = ((uint32_t)__bfloat16_as_ushort(l1) << 16) | __bfloat16_as_ushort(l0);
    pl->y = ((uint32_t)__bfloat16_as_ushort(l3) << 16) | __bfloat16_as_ushort(l2);
}

__global__ void split_kernel(const float* __restrict__ X, const float* __restrict__ W1) {
    int i = blockIdx.x * blockDim.x + threadIdx.x;
    if (i < NNODES * DIN / 4) {
        float4 v = __ldg(&((const float4*)X)[i]);
        uint2 ph, pl;
        split4(v, &ph, &pl);
        ((uint2*)g_Xh)[i] = ph;
        ((uint2*)g_Xl)[i] = pl;
    }
    if (i < DIN * DH / 4) {
        float4 v = __ldg(&((const float4*)W1)[i]);
        uint2 ph, pl;
        split4(v, &ph, &pl);
        ((uint2*)g_W1h)[i] = ph;
        ((uint2*)g_W1l)[i] = pl;
    }
}

// ================= GEMM1 via mma.sync bf16 (3-term split) ==================
// CTA tile 128(m) x 64(n); K chunks of 64, double-buffered cp.async.
// Per stage: Ah 16KB | Al 16KB | Bh 8KB | Bl 8KB = 48KB; 2 stages = 96KB.

#define STAGE_BYTES 49152
#define GEMM_SMEM   (2 * STAGE_BYTES)

__device__ __forceinline__ uint32_t smem_u32(const void* p) {
    uint32_t a;
    asm("{ .reg .u64 t; cvta.to.shared.u64 t, %1; cvt.u32.u64 %0, t; }" : "=r"(a) : "l"(p));
    return a;
}
__device__ __forceinline__ void cp16(uint32_t dst, const void* src) {
    asm volatile("cp.async.ca.shared.global [%0], [%1], 16;" :: "r"(dst), "l"(src));
}
__device__ __forceinline__ void ldmatrix_x4(uint32_t* r, uint32_t addr) {
    asm volatile("ldmatrix.sync.aligned.m8n8.x4.shared.b16 {%0,%1,%2,%3}, [%4];"
                 : "=r"(r[0]), "=r"(r[1]), "=r"(r[2]), "=r"(r[3]) : "r"(addr));
}
__device__ __forceinline__ void ldmatrix_x2t(uint32_t* r, uint32_t addr) {
    asm volatile("ldmatrix.sync.aligned.m8n8.x2.trans.shared.b16 {%0,%1}, [%2];"
                 : "=r"(r[0]), "=r"(r[1]) : "r"(addr));
}
__device__ __forceinline__ void mma_bf16(float* d, const uint32_t* a, const uint32_t* b) {
    asm volatile(
        "mma.sync.aligned.m16n8k16.row.col.f32.bf16.bf16.f32 "
        "{%0,%1,%2,%3}, {%4,%5,%6,%7}, {%8,%9}, {%0,%1,%2,%3};"
        : "+f"(d[0]), "+f"(d[1]), "+f"(d[2]), "+f"(d[3])
        : "r"(a[0]), "r"(a[1]), "r"(a[2]), "r"(a[3]), "r"(b[0]), "r"(b[1]));
}

__device__ __forceinline__ void gemm_prefetch(uint32_t sb, int tid, int bm, int bn, int k0) {
#pragma unroll
    for (int p = 0; p < 4; ++p) {
        int idx = tid + p * 256;
        int row = idx >> 3, c16 = idx & 7;
        uint32_t off = (uint32_t)(row * 128 + c16 * 16);
        off ^= (uint32_t)(row & 7) << 4;
        const __nv_bfloat16* sh = g_Xh + (size_t)(bm + row) * DIN + k0 + c16 * 8;
        const __nv_bfloat16* sl = g_Xl + (size_t)(bm + row) * DIN + k0 + c16 * 8;
        cp16(sb + off, sh);
        cp16(sb + 16384 + off, sl);
    }
#pragma unroll
    for (int p = 0; p < 2; ++p) {
        int idx = tid + p * 256;
        int row = idx >> 3, c16 = idx & 7;
        uint32_t off = (uint32_t)(row * 128 + c16 * 16);
        off ^= (uint32_t)(row & 7) << 4;
        cp16(sb + 32768 + off, g_W1h + (size_t)(k0 + row) * DH + bn + c16 * 8);
        cp16(sb + 40960 + off, g_W1l + (size_t)(k0 + row) * DH + bn + c16 * 8);
    }
    asm volatile("cp.async.commit_group;");
}

__global__ __launch_bounds__(256) void gemm1_mma_kernel() {
    extern __shared__ __align__(1024) char sm[];
    const uint32_t sbase = smem_u32(sm);
    const int tid = threadIdx.x;
    const int wid = tid >> 5, lane = tid & 31;
    const int bm = blockIdx.y * 128;
    const int bn = blockIdx.x * 64;
    const int wm0 = (wid & 3) * 32;
    const int wn0 = (wid >> 2) * 32;

    float d[2][4][4];
#pragma unroll
    for (int mt = 0; mt < 2; ++mt)
#pragma unroll
        for (int nt = 0; nt < 4; ++nt)
#pragma unroll
            for (int u = 0; u < 4; ++u) d[mt][nt][u] = 0.f;

    gemm_prefetch(sbase, tid, bm, bn, 0);

    for (int ch = 0; ch < 8; ++ch) {
        const uint32_t stb = sbase + (uint32_t)(ch & 1) * STAGE_BYTES;
        if (ch < 7) {
            gemm_prefetch(sbase + (uint32_t)((ch + 1) & 1) * STAGE_BYTES, tid, bm, bn, (ch + 1) * 64);
            asm volatile("cp.async.wait_group 1;");
        } else {
            asm volatile("cp.async.wait_group 0;");
        }
        __syncthreads();

#pragma unroll
        for (int ks = 0; ks < 4; ++ks) {
            const int kk = ks * 16;
            uint32_t ah[2][4], al[2][4], bh[4][2], bl[4][2];
#pragma unroll
            for (int mt = 0; mt < 2; ++mt) {
                int row = wm0 + mt * 16 + (lane & 15);
                uint32_t off = (uint32_t)(row * 128 + kk * 2 + ((lane >> 4) << 4));
                off ^= (uint32_t)(row & 7) << 4;
                ldmatrix_x4(ah[mt], stb + off);
                ldmatrix_x4(al[mt], stb + 16384 + off);
            }
#pragma unroll
            for (int nt = 0; nt < 4; ++nt) {
                int row = kk + (lane & 15);
                uint32_t off = (uint32_t)(row * 128 + (wn0 + nt * 8) * 2);
                off ^= (uint32_t)(row & 7) << 4;
                ldmatrix_x2t(bh[nt], stb + 32768 + off);
                ldmatrix_x2t(bl[nt], stb + 40960 + off);
            }
#pragma unroll
            for (int mt = 0; mt < 2; ++mt)
#pragma unroll
                for (int nt = 0; nt < 4; ++nt) {
                    mma_bf16(d[mt][nt], ah[mt], bh[nt]);
                    mma_bf16(d[mt][nt], ah[mt], bl[nt]);
                    mma_bf16(d[mt][nt], al[mt], bh[nt]);
                }
        }
        __syncthreads();
    }

    // ---- epilogue: write fp32 Y1 ----
    const int group = lane >> 2, tig = lane & 3;
#pragma unroll
    for (int mt = 0; mt < 2; ++mt) {
#pragma unroll
        for (int nt = 0; nt < 4; ++nt) {
            int row = bm + wm0 + mt * 16 + group;
            int col = bn + wn0 + nt * 8 + tig * 2;
            float2 v01 = make_float2(d[mt][nt][0], d[mt][nt][1]);
            float2 v23 = make_float2(d[mt][nt][2], d[mt][nt][3]);
            *(float2*)&g_Y1[(size_t)row * DH + col] = v01;
            *(float2*)&g_Y1[(size_t)(row + 8) * DH + col] = v23;
        }
    }
}

// ---------------- prop1: P1[dst] += Y1[src] * (dinv[src]*dinv[dst]) --------
__global__ __launch_bounds__(256) void prop1_kernel(const int* __restrict__ src,
                                                    const int* __restrict__ dst) {
    int w = (blockIdx.x * blockDim.x + threadIdx.x) >> 5;
    int lane = threadIdx.x & 31;
    if (w >= NEDGES) return;
    int s = __ldg(&src[w]);
    int d = __ldg(&dst[w]);
    float nrm = g_dinv[s] * g_dinv[d];
    const float4* yrow = (const float4*)(g_Y1 + (size_t)s * DH);
    float* prow = g_P1 + (size_t)d * DH;
#pragma unroll
    for (int it = 0; it < 2; ++it) {
        int c = lane + it * 32;
        float4 v = __ldg(&yrow[c]);
        float* p = prow + (c << 2);
        asm volatile("red.global.add.v4.f32 [%0], {%1,%2,%3,%4};"
                     :: "l"(p), "f"(v.x * nrm), "f"(v.y * nrm),
                        "f"(v.z * nrm), "f"(v.w * nrm) : "memory");
    }
}

// ---------------- node fuse: h = relu(P1 + Y1*dinv^2 + b1); Y2 = h @ W2 ----
__global__ __launch_bounds__(256) void node2_kernel(const float* __restrict__ b1,
                                                    const float* __restrict__ W2) {
    int node = (blockIdx.x * blockDim.x + threadIdx.x) >> 5;
    int lane = threadIdx.x & 31;
    if (node >= NNODES) return;
    float di = g_dinv[node];
    float di2 = di * di;
    const float* prow = g_P1 + (size_t)node * DH;
    const float* yrow = g_Y1 + (size_t)node * DH;
    const float2* w2 = (const float2*)W2;
    float s0 = 0.f, s1 = 0.f;
#pragma unroll
    for (int j = 0; j < DH / 32; ++j) {
        int d = lane + j * 32;
        float h = prow[d] + yrow[d] * di2 + b1[d];
        h = fmaxf(h, 0.f);
        float2 w = __ldg(&w2[d]);
        s0 = fmaf(h, w.x, s0);
        s1 = fmaf(h, w.y, s1);
    }
#pragma unroll
    for (int off = 16; off > 0; off >>= 1) {
        s0 += __shfl_down_sync(0xffffffffu, s0, off);
        s1 += __shfl_down_sync(0xffffffffu, s1, off);
    }
    if (lane == 0) {
        g_Y2[node * 2 + 0] = s0;
        g_Y2[node * 2 + 1] = s1;
    }
}

// ---------------- prop2 ----------------------------------------------------
__global__ void prop2_kernel(const int* __restrict__ src, const int* __restrict__ dst) {
    int e = blockIdx.x * blockDim.x + threadIdx.x;
    if (e >= NEDGES) return;
    int s = src[e], d = dst[e];
    float nrm = g_dinv[s] * g_dinv[d];
    float2 y = ((const float2*)g_Y2)[s];
    float* p = g_eacc + (size_t)d * 2;
    asm volatile("red.global.add.v2.f32 [%0], {%1,%2};"
                 :: "l"(p), "f"(y.x * nrm), "f"(y.y * nrm) : "memory");
}

// ---------------- finalize emb ---------------------------------------------
__global__ void fin_kernel(const float* __restrict__ b2, float* __restrict__ out) {
    int i = blockIdx.x * blockDim.x + threadIdx.x;
    if (i >= NNODES) return;
    float di = g_dinv[i];
    float di2 = di * di;
    float2 y = ((const float2*)g_Y2)[i];
    float ex = g_eacc[2 * i + 0] + y.x * di2 + b2[0];
    float ey = g_eacc[2 * i + 1] + y.y * di2 + b2[1];
    g_ex[i] = ex;
    g_ey[i] = ey;
    out[2 * i + 0] = ex;
    out[2 * i + 1] = ey;
}

// ---------------- q: symmetric upper-triangular 64x64 tiles ----------------
__device__ __forceinline__ float qval(float dx, float dy) {
    float d2 = fmaf(dx, dx, dy * dy);
    float pw = __powf(d2, BETA);
    float q  = __fdividef(1.0f, fmaf(ALPHA, pw, 1.0f));
    return d2 > 0.0f ? q : 1.0f;
}

__global__ __launch_bounds__(256) void q_kernel(float* __restrict__ qout) {
    __shared__ float qs[64][65];
    int b = blockIdx.x;
    int r = (int)((257.0f - sqrtf(66049.0f - 8.0f * (float)b)) * 0.5f);
    while ((r + 1) * 128 - ((r + 1) * r) / 2 <= b) ++r;
    while (r * 128 - (r * (r - 1)) / 2 > b) --r;
    int S = r * 128 - (r * (r - 1)) / 2;
    int bi = r;
    int bj = r + (b - S);
    int ty = threadIdx.x >> 4, tx = threadIdx.x & 15;
    int r0 = ty * 4, c0 = tx * 4;
    bool diag = (bi == bj);

    float4 xj = *(const float4*)&g_ex[bj * 64 + c0];
    float4 yj = *(const float4*)&g_ey[bj * 64 + c0];
#pragma unroll
    for (int u = 0; u < 4; ++u) {
        float xi = g_ex[bi * 64 + r0 + u];
        float yi = g_ey[bi * 64 + r0 + u];
        float4 v;
        v.x = qval(xi - xj.x, yi - yj.x);
        v.y = qval(xi - xj.y, yi - yj.y);
        v.z = qval(xi - xj.z, yi - yj.z);
        v.w = qval(xi - xj.w, yi - yj.w);
        *(float4*)&qout[(size_t)(bi * 64 + r0 + u) * NNODES + bj * 64 + c0] = v;
        if (!diag) {
            qs[r0 + u][c0 + 0] = v.x;
            qs[r0 + u][c0 + 1] = v.y;
            qs[r0 + u][c0 + 2] = v.z;
            qs[r0 + u][c0 + 3] = v.w;
        }
    }
    if (!diag) {
        __syncthreads();
#pragma unroll
        for (int u = 0; u < 4; ++u) {
            float4 v;
            v.x = qs[c0 + 0][r0 + u];
            v.y = qs[c0 + 1][r0 + u];
            v.z = qs[c0 + 2][r0 + u];
            v.w = qs[c0 + 3][r0 + u];
            *(float4*)&qout[(size_t)(bj * 64 + r0 + u) * NNODES + bi * 64 + c0] = v;
        }
    }
}

// ---------------------------------------------------------------------------
extern "C" void kernel_launch(void* const* d_in, const int* in_sizes, int n_in,
                              void* d_out, int out_size) {
    const float* X  = (const float*)d_in[0];
    const int*   ei = (const int*)  d_in[1];
    const float* W1 = (const float*)d_in[2];
    const float* b1 = (const float*)d_in[3];
    const float* W2 = (const float*)d_in[4];
    const float* b2 = (const float*)d_in[5];
    float* out = (float*)d_out;
    (void)in_sizes; (void)n_in; (void)out_size;

    const int* src = ei;
    const int* dst = ei + NEDGES;

    cudaFuncSetAttribute(gemm1_mma_kernel,
                         cudaFuncAttributeMaxDynamicSharedMemorySize, GEMM_SMEM);

    zero_kernel<<<(NNODES * DH / 4 + 255) / 256, 256>>>();
    deg_kernel<<<NEDGES / 256, 256>>>(dst);
    dinv_kernel<<<NNODES / 256, 256>>>();
    split_kernel<<<NNODES * DIN / 4 / 256, 256>>>(X, W1);
    gemm1_mma_kernel<<<dim3(DH / 64, NNODES / 128), 256, GEMM_SMEM>>>();
    prop1_kernel<<<NEDGES * 32 / 256, 256>>>(src, dst);
    node2_kernel<<<NNODES * 32 / 256, 256>>>(b1, W2);
    prop2_kernel<<<NEDGES / 256, 256>>>(src, dst);
    fin_kernel<<<NNODES / 256, 256>>>(b2, out);
    q_kernel<<<128 * 129 / 2, 256>>>(out + NNODES * 2);
}

// round 8
// speedup vs baseline: 1.2531x; 1.0530x over previous
#include <cuda_runtime.h>
#include <cuda_bf16.h>
#include <cstdint>

#define NNODES 8192
#define NEDGES 262144
#define DIN    512
#define DH     256
#define ALPHA  0.1520f
#define BETA   0.7900f

// ---------------- scratch (device globals; no allocation allowed) ----------
__device__ int   g_cnt [NNODES];
__device__ int   g_rowstart[NNODES + 1];
__device__ int   g_cursor  [NNODES];
__device__ float g_dinv[NNODES];
__device__ int   g_esrc[NEDGES];
__device__ float g_enrm[NEDGES];
__device__ __nv_bfloat16 g_Xh [NNODES * DIN];
__device__ __nv_bfloat16 g_Xl [NNODES * DIN];
__device__ __nv_bfloat16 g_W1h[DIN * DH];
__device__ __nv_bfloat16 g_W1l[DIN * DH];
__device__ float g_Y1  [NNODES * DH];   // X @ W1 (fp32)
__device__ float g_Y2  [NNODES * 2];
__device__ float g_ex  [NNODES];
__device__ float g_ey  [NNODES];

// ---------------- zero counters (every replay) -----------------------------
__global__ void zero_small_kernel() {
    int i = blockIdx.x * blockDim.x + threadIdx.x;
    if (i < NNODES) g_cnt[i] = 0;
}

__global__ void deg_kernel(const int* __restrict__ dst) {
    int e = blockIdx.x * blockDim.x + threadIdx.x;
    if (e < NEDGES) atomicAdd(&g_cnt[dst[e]], 1);
}

__global__ void dinv_kernel() {
    int i = blockIdx.x * blockDim.x + threadIdx.x;
    if (i < NNODES) g_dinv[i] = rsqrtf((float)g_cnt[i] + 1.0f);
}

// ---------------- exclusive scan over 8192 counts (1 block, 1024 thr) ------
__global__ __launch_bounds__(1024) void scan_kernel() {
    __shared__ int wsum[32];
    const int tid = threadIdx.x;
    const int lane = tid & 31, wid = tid >> 5;
    const int base = tid * 8;
    int loc[8];
    int s = 0;
#pragma unroll
    for (int j = 0; j < 8; ++j) { loc[j] = s; s += g_cnt[base + j]; }
    // inclusive warp scan of thread totals
    int ws = s;
#pragma unroll
    for (int off = 1; off < 32; off <<= 1) {
        int v = __shfl_up_sync(0xffffffffu, ws, off);
        if (lane >= off) ws += v;
    }
    if (lane == 31) wsum[wid] = ws;
    __syncthreads();
    if (wid == 0) {
        int v = (lane < 32) ? wsum[lane] : 0;
        int iv = v;
#pragma unroll
        for (int off = 1; off < 32; off <<= 1) {
            int t = __shfl_up_sync(0xffffffffu, iv, off);
            if (lane >= off) iv += t;
        }
        wsum[lane] = iv - v;   // exclusive warp base
    }
    __syncthreads();
    int tbase = wsum[wid] + (ws - s);   // exclusive prefix for this thread
#pragma unroll
    for (int j = 0; j < 8; ++j) {
        int rs = tbase + loc[j];
        g_rowstart[base + j] = rs;
        g_cursor[base + j]   = rs;
    }
    if (tid == 1023) g_rowstart[NNODES] = NEDGES;
}

// ---------------- scatter edges into CSR (by dst) --------------------------
__global__ void scatter_kernel(const int* __restrict__ src, const int* __restrict__ dst) {
    int e = blockIdx.x * blockDim.x + threadIdx.x;
    if (e >= NEDGES) return;
    int s = src[e], d = dst[e];
    int pos = atomicAdd(&g_cursor[d], 1);
    g_esrc[pos] = s;
    g_enrm[pos] = g_dinv[s] * g_dinv[d];
}

// ---------------- bf16 split pre-pass (X and W1 fused) ---------------------
__device__ __forceinline__ void split4(float4 v, uint2* ph, uint2* pl) {
    __nv_bfloat16 h0 = __float2bfloat16_rn(v.x);
    __nv_bfloat16 h1 = __float2bfloat16_rn(v.y);
    __nv_bfloat16 h2 = __float2bfloat16_rn(v.z);
    __nv_bfloat16 h3 = __float2bfloat16_rn(v.w);
    __nv_bfloat16 l0 = __float2bfloat16_rn(v.x - __bfloat162float(h0));
    __nv_bfloat16 l1 = __float2bfloat16_rn(v.y - __bfloat162float(h1));
    __nv_bfloat16 l2 = __float2bfloat16_rn(v.z - __bfloat162float(h2));
    __nv_bfloat16 l3 = __float2bfloat16_rn(v.w - __bfloat162float(h3));
    ph->x = ((uint32_t)__bfloat16_as_ushort(h1) << 16) | __bfloat16_as_ushort(h0);
    ph->y = ((uint32_t)__bfloat16_as_ushort(h3) << 16) | __bfloat16_as_ushort(h2);
    pl->x = ((uint32_t)__bfloat16_as_ushort(l1) << 16) | __bfloat16_as_ushort(l0);
    pl->y = ((uint32_t)__bfloat16_as_ushort(l3) << 16) | __bfloat16_as_ushort(l2);
}

__global__ void split_kernel(const float* __restrict__ X, const float* __restrict__ W1) {
    int i = blockIdx.x * blockDim.x + threadIdx.x;
    if (i < NNODES * DIN / 4) {
        float4 v = __ldg(&((const float4*)X)[i]);
        uint2 ph, pl;
        split4(v, &ph, &pl);
        ((uint2*)g_Xh)[i] = ph;
        ((uint2*)g_Xl)[i] = pl;
    }
    if (i < DIN * DH / 4) {
        float4 v = __ldg(&((const float4*)W1)[i]);
        uint2 ph, pl;
        split4(v, &ph, &pl);
        ((uint2*)g_W1h)[i] = ph;
        ((uint2*)g_W1l)[i] = pl;
    }
}

// ================= GEMM1 via mma.sync bf16 (3-term split) ==================
#define STAGE_BYTES 49152
#define GEMM_SMEM   (2 * STAGE_BYTES)

__device__ __forceinline__ uint32_t smem_u32(const void* p) {
    uint32_t a;
    asm("{ .reg .u64 t; cvta.to.shared.u64 t, %1; cvt.u32.u64 %0, t; }" : "=r"(a) : "l"(p));
    return a;
}
__device__ __forceinline__ void cp16(uint32_t dst, const void* src) {
    asm volatile("cp.async.ca.shared.global [%0], [%1], 16;" :: "r"(dst), "l"(src));
}
__device__ __forceinline__ void ldmatrix_x4(uint32_t* r, uint32_t addr) {
    asm volatile("ldmatrix.sync.aligned.m8n8.x4.shared.b16 {%0,%1,%2,%3}, [%4];"
                 : "=r"(r[0]), "=r"(r[1]), "=r"(r[2]), "=r"(r[3]) : "r"(addr));
}
__device__ __forceinline__ void ldmatrix_x2t(uint32_t* r, uint32_t addr) {
    asm volatile("ldmatrix.sync.aligned.m8n8.x2.trans.shared.b16 {%0,%1}, [%2];"
                 : "=r"(r[0]), "=r"(r[1]) : "r"(addr));
}
__device__ __forceinline__ void mma_bf16(float* d, const uint32_t* a, const uint32_t* b) {
    asm volatile(
        "mma.sync.aligned.m16n8k16.row.col.f32.bf16.bf16.f32 "
        "{%0,%1,%2,%3}, {%4,%5,%6,%7}, {%8,%9}, {%0,%1,%2,%3};"
        : "+f"(d[0]), "+f"(d[1]), "+f"(d[2]), "+f"(d[3])
        : "r"(a[0]), "r"(a[1]), "r"(a[2]), "r"(a[3]), "r"(b[0]), "r"(b[1]));
}

__device__ __forceinline__ void gemm_prefetch(uint32_t sb, int tid, int bm, int bn, int k0) {
#pragma unroll
    for (int p = 0; p < 4; ++p) {
        int idx = tid + p * 256;
        int row = idx >> 3, c16 = idx & 7;
        uint32_t off = (uint32_t)(row * 128 + c16 * 16);
        off ^= (uint32_t)(row & 7) << 4;
        cp16(sb + off,         g_Xh + (size_t)(bm + row) * DIN + k0 + c16 * 8);
        cp16(sb + 16384 + off, g_Xl + (size_t)(bm + row) * DIN + k0 + c16 * 8);
    }
#pragma unroll
    for (int p = 0; p < 2; ++p) {
        int idx = tid + p * 256;
        int row = idx >> 3, c16 = idx & 7;
        uint32_t off = (uint32_t)(row * 128 + c16 * 16);
        off ^= (uint32_t)(row & 7) << 4;
        cp16(sb + 32768 + off, g_W1h + (size_t)(k0 + row) * DH + bn + c16 * 8);
        cp16(sb + 40960 + off, g_W1l + (size_t)(k0 + row) * DH + bn + c16 * 8);
    }
    asm volatile("cp.async.commit_group;");
}

__global__ __launch_bounds__(256) void gemm1_mma_kernel() {
    extern __shared__ __align__(1024) char sm[];
    const uint32_t sbase = smem_u32(sm);
    const int tid = threadIdx.x;
    const int wid = tid >> 5, lane = tid & 31;
    const int bm = blockIdx.y * 128;
    const int bn = blockIdx.x * 64;
    const int wm0 = (wid & 3) * 32;
    const int wn0 = (wid >> 2) * 32;

    float d[2][4][4];
#pragma unroll
    for (int mt = 0; mt < 2; ++mt)
#pragma unroll
        for (int nt = 0; nt < 4; ++nt)
#pragma unroll
            for (int u = 0; u < 4; ++u) d[mt][nt][u] = 0.f;

    gemm_prefetch(sbase, tid, bm, bn, 0);

    for (int ch = 0; ch < 8; ++ch) {
        const uint32_t stb = sbase + (uint32_t)(ch & 1) * STAGE_BYTES;
        if (ch < 7) {
            gemm_prefetch(sbase + (uint32_t)((ch + 1) & 1) * STAGE_BYTES, tid, bm, bn, (ch + 1) * 64);
            asm volatile("cp.async.wait_group 1;");
        } else {
            asm volatile("cp.async.wait_group 0;");
        }
        __syncthreads();

#pragma unroll
        for (int ks = 0; ks < 4; ++ks) {
            const int kk = ks * 16;
            uint32_t ah[2][4], al[2][4], bh[4][2], bl[4][2];
#pragma unroll
            for (int mt = 0; mt < 2; ++mt) {
                int row = wm0 + mt * 16 + (lane & 15);
                uint32_t off = (uint32_t)(row * 128 + kk * 2 + ((lane >> 4) << 4));
                off ^= (uint32_t)(row & 7) << 4;
                ldmatrix_x4(ah[mt], stb + off);
                ldmatrix_x4(al[mt], stb + 16384 + off);
            }
#pragma unroll
            for (int nt = 0; nt < 4; ++nt) {
                int row = kk + (lane & 15);
                uint32_t off = (uint32_t)(row * 128 + (wn0 + nt * 8) * 2);
                off ^= (uint32_t)(row & 7) << 4;
                ldmatrix_x2t(bh[nt], stb + 32768 + off);
                ldmatrix_x2t(bl[nt], stb + 40960 + off);
            }
#pragma unroll
            for (int mt = 0; mt < 2; ++mt)
#pragma unroll
                for (int nt = 0; nt < 4; ++nt) {
                    mma_bf16(d[mt][nt], ah[mt], bh[nt]);
                    mma_bf16(d[mt][nt], ah[mt], bl[nt]);
                    mma_bf16(d[mt][nt], al[mt], bh[nt]);
                }
        }
        __syncthreads();
    }

    const int group = lane >> 2, tig = lane & 3;
#pragma unroll
    for (int mt = 0; mt < 2; ++mt) {
#pragma unroll
        for (int nt = 0; nt < 4; ++nt) {
            int row = bm + wm0 + mt * 16 + group;
            int col = bn + wn0 + nt * 8 + tig * 2;
            *(float2*)&g_Y1[(size_t)row * DH + col] = make_float2(d[mt][nt][0], d[mt][nt][1]);
            *(float2*)&g_Y1[(size_t)(row + 8) * DH + col] = make_float2(d[mt][nt][2], d[mt][nt][3]);
        }
    }
}

// ------ fused prop1 + self-loop + bias + relu + @W2 (warp per dst node) ----
// lane owns columns [lane*8, lane*8+8): acc in 8 regs, 2x LDG.128 per edge.
__global__ __launch_bounds__(256) void prop1node2_kernel(const float* __restrict__ b1,
                                                         const float* __restrict__ W2) {
    const int node = (blockIdx.x * blockDim.x + threadIdx.x) >> 5;
    const int lane = threadIdx.x & 31;
    if (node >= NNODES) return;
    const int e0 = g_rowstart[node];
    const int e1 = g_rowstart[node + 1];

    float4 a0 = make_float4(0.f, 0.f, 0.f, 0.f);
    float4 a1 = make_float4(0.f, 0.f, 0.f, 0.f);
    const int fi = 2 * lane;           // float4 index of lane's first quad

    int e = e0;
    for (; e + 2 <= e1; e += 2) {
        int   sA = __ldg(&g_esrc[e]);
        int   sB = __ldg(&g_esrc[e + 1]);
        float nA = __ldg(&g_enrm[e]);
        float nB = __ldg(&g_enrm[e + 1]);
        const float4* rA = (const float4*)(g_Y1 + (size_t)sA * DH);
        const float4* rB = (const float4*)(g_Y1 + (size_t)sB * DH);
        float4 vA0 = __ldg(&rA[fi]),     vB0 = __ldg(&rB[fi]);
        float4 vA1 = __ldg(&rA[fi + 1]), vB1 = __ldg(&rB[fi + 1]);
        a0.x = fmaf(nA, vA0.x, a0.x); a0.y = fmaf(nA, vA0.y, a0.y);
        a0.z = fmaf(nA, vA0.z, a0.z); a0.w = fmaf(nA, vA0.w, a0.w);
        a1.x = fmaf(nA, vA1.x, a1.x); a1.y = fmaf(nA, vA1.y, a1.y);
        a1.z = fmaf(nA, vA1.z, a1.z); a1.w = fmaf(nA, vA1.w, a1.w);
        a0.x = fmaf(nB, vB0.x, a0.x); a0.y = fmaf(nB, vB0.y, a0.y);
        a0.z = fmaf(nB, vB0.z, a0.z); a0.w = fmaf(nB, vB0.w, a0.w);
        a1.x = fmaf(nB, vB1.x, a1.x); a1.y = fmaf(nB, vB1.y, a1.y);
        a1.z = fmaf(nB, vB1.z, a1.z); a1.w = fmaf(nB, vB1.w, a1.w);
    }
    if (e < e1) {
        int   sA = __ldg(&g_esrc[e]);
        float nA = __ldg(&g_enrm[e]);
        const float4* rA = (const float4*)(g_Y1 + (size_t)sA * DH);
        float4 vA0 = __ldg(&rA[fi]), vA1 = __ldg(&rA[fi + 1]);
        a0.x = fmaf(nA, vA0.x, a0.x); a0.y = fmaf(nA, vA0.y, a0.y);
        a0.z = fmaf(nA, vA0.z, a0.z); a0.w = fmaf(nA, vA0.w, a0.w);
        a1.x = fmaf(nA, vA1.x, a1.x); a1.y = fmaf(nA, vA1.y, a1.y);
        a1.z = fmaf(nA, vA1.z, a1.z); a1.w = fmaf(nA, vA1.w, a1.w);
    }

    // self loop
    float di = g_dinv[node];
    float di2 = di * di;
    const float4* rs = (const float4*)(g_Y1 + (size_t)node * DH);
    float4 s0v = __ldg(&rs[fi]), s1v = __ldg(&rs[fi + 1]);
    a0.x = fmaf(di2, s0v.x, a0.x); a0.y = fmaf(di2, s0v.y, a0.y);
    a0.z = fmaf(di2, s0v.z, a0.z); a0.w = fmaf(di2, s0v.w, a0.w);
    a1.x = fmaf(di2, s1v.x, a1.x); a1.y = fmaf(di2, s1v.y, a1.y);
    a1.z = fmaf(di2, s1v.z, a1.z); a1.w = fmaf(di2, s1v.w, a1.w);

    // bias + relu + dot with W2 columns
    float4 b0v = __ldg(&((const float4*)b1)[fi]);
    float4 b1v = __ldg(&((const float4*)b1)[fi + 1]);
    float h[8];
    h[0] = fmaxf(a0.x + b0v.x, 0.f); h[1] = fmaxf(a0.y + b0v.y, 0.f);
    h[2] = fmaxf(a0.z + b0v.z, 0.f); h[3] = fmaxf(a0.w + b0v.w, 0.f);
    h[4] = fmaxf(a1.x + b1v.x, 0.f); h[5] = fmaxf(a1.y + b1v.y, 0.f);
    h[6] = fmaxf(a1.z + b1v.z, 0.f); h[7] = fmaxf(a1.w + b1v.w, 0.f);
    float p0 = 0.f, p1 = 0.f;
#pragma unroll
    for (int j = 0; j < 8; ++j) {
        float2 w = __ldg(&((const float2*)W2)[lane * 8 + j]);
        p0 = fmaf(h[j], w.x, p0);
        p1 = fmaf(h[j], w.y, p1);
    }
#pragma unroll
    for (int off = 16; off > 0; off >>= 1) {
        p0 += __shfl_down_sync(0xffffffffu, p0, off);
        p1 += __shfl_down_sync(0xffffffffu, p1, off);
    }
    if (lane == 0) {
        g_Y2[node * 2 + 0] = p0;
        g_Y2[node * 2 + 1] = p1;
    }
}

// ---------------- fused prop2 + finalize (warp per dst node) ---------------
__global__ __launch_bounds__(256) void prop2fin_kernel(const float* __restrict__ b2,
                                                       float* __restrict__ out) {
    const int node = (blockIdx.x * blockDim.x + threadIdx.x) >> 5;
    const int lane = threadIdx.x & 31;
    if (node >= NNODES) return;
    const int e0 = g_rowstart[node];
    const int e1 = g_rowstart[node + 1];
    float sx = 0.f, sy = 0.f;
    for (int e = e0 + lane; e < e1; e += 32) {
        int s = __ldg(&g_esrc[e]);
        float n = __ldg(&g_enrm[e]);
        float2 y = __ldg(&((const float2*)g_Y2)[s]);
        sx = fmaf(n, y.x, sx);
        sy = fmaf(n, y.y, sy);
    }
#pragma unroll
    for (int off = 16; off > 0; off >>= 1) {
        sx += __shfl_down_sync(0xffffffffu, sx, off);
        sy += __shfl_down_sync(0xffffffffu, sy, off);
    }
    if (lane == 0) {
        float di = g_dinv[node];
        float di2 = di * di;
        float2 y = __ldg(&((const float2*)g_Y2)[node]);
        float ex = sx + y.x * di2 + b2[0];
        float ey = sy + y.y * di2 + b2[1];
        g_ex[node] = ex;
        g_ey[node] = ey;
        out[2 * node + 0] = ex;
        out[2 * node + 1] = ey;
    }
}

// ---------------- q: symmetric upper-triangular 64x64 tiles ----------------
__device__ __forceinline__ float qval(float dx, float dy) {
    float d2 = fmaf(dx, dx, dy * dy);
    float pw = __powf(d2, BETA);
    float q  = __fdividef(1.0f, fmaf(ALPHA, pw, 1.0f));
    return d2 > 0.0f ? q : 1.0f;
}

__global__ __launch_bounds__(256) void q_kernel(float* __restrict__ qout) {
    __shared__ float qs[64][65];
    int b = blockIdx.x;
    int r = (int)((257.0f - sqrtf(66049.0f - 8.0f * (float)b)) * 0.5f);
    while ((r + 1) * 128 - ((r + 1) * r) / 2 <= b) ++r;
    while (r * 128 - (r * (r - 1)) / 2 > b) --r;
    int S = r * 128 - (r * (r - 1)) / 2;
    int bi = r;
    int bj = r + (b - S);
    int ty = threadIdx.x >> 4, tx = threadIdx.x & 15;
    int r0 = ty * 4, c0 = tx * 4;
    bool diag = (bi == bj);

    float4 xj = *(const float4*)&g_ex[bj * 64 + c0];
    float4 yj = *(const float4*)&g_ey[bj * 64 + c0];
#pragma unroll
    for (int u = 0; u < 4; ++u) {
        float xi = g_ex[bi * 64 + r0 + u];
        float yi = g_ey[bi * 64 + r0 + u];
        float4 v;
        v.x = qval(xi - xj.x, yi - yj.x);
        v.y = qval(xi - xj.y, yi - yj.y);
        v.z = qval(xi - xj.z, yi - yj.z);
        v.w = qval(xi - xj.w, yi - yj.w);
        *(float4*)&qout[(size_t)(bi * 64 + r0 + u) * NNODES + bj * 64 + c0] = v;
        if (!diag) {
            qs[r0 + u][c0 + 0] = v.x;
            qs[r0 + u][c0 + 1] = v.y;
            qs[r0 + u][c0 + 2] = v.z;
            qs[r0 + u][c0 + 3] = v.w;
        }
    }
    if (!diag) {
        __syncthreads();
#pragma unroll
        for (int u = 0; u < 4; ++u) {
            float4 v;
            v.x = qs[c0 + 0][r0 + u];
            v.y = qs[c0 + 1][r0 + u];
            v.z = qs[c0 + 2][r0 + u];
            v.w = qs[c0 + 3][r0 + u];
            *(float4*)&qout[(size_t)(bj * 64 + r0 + u) * NNODES + bi * 64 + c0] = v;
        }
    }
}

// ---------------------------------------------------------------------------
extern "C" void kernel_launch(void* const* d_in, const int* in_sizes, int n_in,
                              void* d_out, int out_size) {
    const float* X  = (const float*)d_in[0];
    const int*   ei = (const int*)  d_in[1];
    const float* W1 = (const float*)d_in[2];
    const float* b1 = (const float*)d_in[3];
    const float* W2 = (const float*)d_in[4];
    const float* b2 = (const float*)d_in[5];
    float* out = (float*)d_out;
    (void)in_sizes; (void)n_in; (void)out_size;

    const int* src = ei;
    const int* dst = ei + NEDGES;

    cudaFuncSetAttribute(gemm1_mma_kernel,
                         cudaFuncAttributeMaxDynamicSharedMemorySize, GEMM_SMEM);

    zero_small_kernel<<<NNODES / 256, 256>>>();
    deg_kernel<<<NEDGES / 256, 256>>>(dst);
    dinv_kernel<<<NNODES / 256, 256>>>();
    scan_kernel<<<1, 1024>>>();
    scatter_kernel<<<NEDGES / 256, 256>>>(src, dst);
    split_kernel<<<NNODES * DIN / 4 / 256, 256>>>(X, W1);
    gemm1_mma_kernel<<<dim3(DH / 64, NNODES / 128), 256, GEMM_SMEM>>>();
    prop1node2_kernel<<<NNODES * 32 / 256, 256>>>(b1, W2);
    prop2fin_kernel<<<NNODES * 32 / 256, 256>>>(b2, out);
    q_kernel<<<128 * 129 / 2, 256>>>(out + NNODES * 2);
}

// round 9
// speedup vs baseline: 1.3381x; 1.0679x over previous
#include <cuda_runtime.h>
#include <cuda_bf16.h>
#include <cstdint>

#define NNODES 8192
#define NEDGES 262144
#define DIN    512
#define DH     256
#define ALPHA  0.1520f
#define BETA   0.7900f
#define CAPLG  7
#define CAP    128   // padded bin capacity per dst node (mean deg = 32)

// ---------------- scratch (device globals; no allocation allowed) ----------
__device__ int   g_cnt [NNODES];
__device__ int   g_cur [NNODES];
__device__ float g_dinv[NNODES];
__device__ int2  g_edge[NNODES * CAP];   // {src, bitcast(nrm)} per slot
__device__ __nv_bfloat16 g_Xh [NNODES * DIN];
__device__ __nv_bfloat16 g_Xl [NNODES * DIN];
__device__ __nv_bfloat16 g_W1h[DIN * DH];
__device__ __nv_bfloat16 g_W1l[DIN * DH];
__device__ float g_Y1  [NNODES * DH];   // X @ W1 (fp32)
__device__ float g_Y2  [NNODES * 2];
__device__ float g_ex  [NNODES];
__device__ float g_ey  [NNODES];

// ---------------- zero counters (every replay) -----------------------------
__global__ void zero_small_kernel() {
    int i = blockIdx.x * blockDim.x + threadIdx.x;
    if (i < NNODES) { g_cnt[i] = 0; g_cur[i] = 0; }
}

__global__ void deg_kernel(const int* __restrict__ dst) {
    int e = blockIdx.x * blockDim.x + threadIdx.x;
    if (e < NEDGES) atomicAdd(&g_cnt[dst[e]], 1);
}

__global__ void dinv_kernel() {
    int i = blockIdx.x * blockDim.x + threadIdx.x;
    if (i < NNODES) g_dinv[i] = rsqrtf((float)g_cnt[i] + 1.0f);
}

// ---------------- scatter edges into padded bins (by dst) ------------------
__global__ void scatter_kernel(const int* __restrict__ src, const int* __restrict__ dst) {
    int e = blockIdx.x * blockDim.x + threadIdx.x;
    if (e >= NEDGES) return;
    int s = src[e], d = dst[e];
    int pos = atomicAdd(&g_cur[d], 1);
    float nrm = g_dinv[s] * g_dinv[d];
    int2 pk;
    pk.x = s;
    pk.y = __float_as_int(nrm);
    g_edge[(d << CAPLG) + pos] = pk;
}

// ---------------- bf16 split pre-pass (X and W1 fused) ---------------------
__device__ __forceinline__ void split4(float4 v, uint2* ph, uint2* pl) {
    __nv_bfloat16 h0 = __float2bfloat16_rn(v.x);
    __nv_bfloat16 h1 = __float2bfloat16_rn(v.y);
    __nv_bfloat16 h2 = __float2bfloat16_rn(v.z);
    __nv_bfloat16 h3 = __float2bfloat16_rn(v.w);
    __nv_bfloat16 l0 = __float2bfloat16_rn(v.x - __bfloat162float(h0));
    __nv_bfloat16 l1 = __float2bfloat16_rn(v.y - __bfloat162float(h1));
    __nv_bfloat16 l2 = __float2bfloat16_rn(v.z - __bfloat162float(h2));
    __nv_bfloat16 l3 = __float2bfloat16_rn(v.w - __bfloat162float(h3));
    ph->x = ((uint32_t)__bfloat16_as_ushort(h1) << 16) | __bfloat16_as_ushort(h0);
    ph->y = ((uint32_t)__bfloat16_as_ushort(h3) << 16) | __bfloat16_as_ushort(h2);
    pl->x = ((uint32_t)__bfloat16_as_ushort(l1) << 16) | __bfloat16_as_ushort(l0);
    pl->y = ((uint32_t)__bfloat16_as_ushort(l3) << 16) | __bfloat16_as_ushort(l2);
}

__global__ void split_kernel(const float* __restrict__ X, const float* __restrict__ W1) {
    int i = blockIdx.x * blockDim.x + threadIdx.x;
    if (i < NNODES * DIN / 4) {
        float4 v = __ldg(&((const float4*)X)[i]);
        uint2 ph, pl;
        split4(v, &ph, &pl);
        ((uint2*)g_Xh)[i] = ph;
        ((uint2*)g_Xl)[i] = pl;
    }
    if (i < DIN * DH / 4) {
        float4 v = __ldg(&((const float4*)W1)[i]);
        uint2 ph, pl;
        split4(v, &ph, &pl);
        ((uint2*)g_W1h)[i] = ph;
        ((uint2*)g_W1l)[i] = pl;
    }
}

// ================= GEMM1 via mma.sync bf16 (3-term split) ==================
#define STAGE_BYTES 49152
#define GEMM_SMEM   (2 * STAGE_BYTES)

__device__ __forceinline__ uint32_t smem_u32(const void* p) {
    uint32_t a;
    asm("{ .reg .u64 t; cvta.to.shared.u64 t, %1; cvt.u32.u64 %0, t; }" : "=r"(a) : "l"(p));
    return a;
}
__device__ __forceinline__ void cp16(uint32_t dst, const void* src) {
    asm volatile("cp.async.ca.shared.global [%0], [%1], 16;" :: "r"(dst), "l"(src));
}
__device__ __forceinline__ void ldmatrix_x4(uint32_t* r, uint32_t addr) {
    asm volatile("ldmatrix.sync.aligned.m8n8.x4.shared.b16 {%0,%1,%2,%3}, [%4];"
                 : "=r"(r[0]), "=r"(r[1]), "=r"(r[2]), "=r"(r[3]) : "r"(addr));
}
__device__ __forceinline__ void ldmatrix_x2t(uint32_t* r, uint32_t addr) {
    asm volatile("ldmatrix.sync.aligned.m8n8.x2.trans.shared.b16 {%0,%1}, [%2];"
                 : "=r"(r[0]), "=r"(r[1]) : "r"(addr));
}
__device__ __forceinline__ void mma_bf16(float* d, const uint32_t* a, const uint32_t* b) {
    asm volatile(
        "mma.sync.aligned.m16n8k16.row.col.f32.bf16.bf16.f32 "
        "{%0,%1,%2,%3}, {%4,%5,%6,%7}, {%8,%9}, {%0,%1,%2,%3};"
        : "+f"(d[0]), "+f"(d[1]), "+f"(d[2]), "+f"(d[3])
        : "r"(a[0]), "r"(a[1]), "r"(a[2]), "r"(a[3]), "r"(b[0]), "r"(b[1]));
}

__device__ __forceinline__ void gemm_prefetch(uint32_t sb, int tid, int bm, int bn, int k0) {
#pragma unroll
    for (int p = 0; p < 4; ++p) {
        int idx = tid + p * 256;
        int row = idx >> 3, c16 = idx & 7;
        uint32_t off = (uint32_t)(row * 128 + c16 * 16);
        off ^= (uint32_t)(row & 7) << 4;
        cp16(sb + off,         g_Xh + (size_t)(bm + row) * DIN + k0 + c16 * 8);
        cp16(sb + 16384 + off, g_Xl + (size_t)(bm + row) * DIN + k0 + c16 * 8);
    }
#pragma unroll
    for (int p = 0; p < 2; ++p) {
        int idx = tid + p * 256;
        int row = idx >> 3, c16 = idx & 7;
        uint32_t off = (uint32_t)(row * 128 + c16 * 16);
        off ^= (uint32_t)(row & 7) << 4;
        cp16(sb + 32768 + off, g_W1h + (size_t)(k0 + row) * DH + bn + c16 * 8);
        cp16(sb + 40960 + off, g_W1l + (size_t)(k0 + row) * DH + bn + c16 * 8);
    }
    asm volatile("cp.async.commit_group;");
}

__global__ __launch_bounds__(256) void gemm1_mma_kernel() {
    extern __shared__ __align__(1024) char sm[];
    const uint32_t sbase = smem_u32(sm);
    const int tid = threadIdx.x;
    const int wid = tid >> 5, lane = tid & 31;
    const int bm = blockIdx.y * 128;
    const int bn = blockIdx.x * 64;
    const int wm0 = (wid & 3) * 32;
    const int wn0 = (wid >> 2) * 32;

    float d[2][4][4];
#pragma unroll
    for (int mt = 0; mt < 2; ++mt)
#pragma unroll
        for (int nt = 0; nt < 4; ++nt)
#pragma unroll
            for (int u = 0; u < 4; ++u) d[mt][nt][u] = 0.f;

    gemm_prefetch(sbase, tid, bm, bn, 0);

    for (int ch = 0; ch < 8; ++ch) {
        const uint32_t stb = sbase + (uint32_t)(ch & 1) * STAGE_BYTES;
        if (ch < 7) {
            gemm_prefetch(sbase + (uint32_t)((ch + 1) & 1) * STAGE_BYTES, tid, bm, bn, (ch + 1) * 64);
            asm volatile("cp.async.wait_group 1;");
        } else {
            asm volatile("cp.async.wait_group 0;");
        }
        __syncthreads();

#pragma unroll
        for (int ks = 0; ks < 4; ++ks) {
            const int kk = ks * 16;
            uint32_t ah[2][4], al[2][4], bh[4][2], bl[4][2];
#pragma unroll
            for (int mt = 0; mt < 2; ++mt) {
                int row = wm0 + mt * 16 + (lane & 15);
                uint32_t off = (uint32_t)(row * 128 + kk * 2 + ((lane >> 4) << 4));
                off ^= (uint32_t)(row & 7) << 4;
                ldmatrix_x4(ah[mt], stb + off);
                ldmatrix_x4(al[mt], stb + 16384 + off);
            }
#pragma unroll
            for (int nt = 0; nt < 4; ++nt) {
                int row = kk + (lane & 15);
                uint32_t off = (uint32_t)(row * 128 + (wn0 + nt * 8) * 2);
                off ^= (uint32_t)(row & 7) << 4;
                ldmatrix_x2t(bh[nt], stb + 32768 + off);
                ldmatrix_x2t(bl[nt], stb + 40960 + off);
            }
#pragma unroll
            for (int mt = 0; mt < 2; ++mt)
#pragma unroll
                for (int nt = 0; nt < 4; ++nt) {
                    mma_bf16(d[mt][nt], ah[mt], bh[nt]);
                    mma_bf16(d[mt][nt], ah[mt], bl[nt]);
                    mma_bf16(d[mt][nt], al[mt], bh[nt]);
                }
        }
        __syncthreads();
    }

    const int group = lane >> 2, tig = lane & 3;
#pragma unroll
    for (int mt = 0; mt < 2; ++mt) {
#pragma unroll
        for (int nt = 0; nt < 4; ++nt) {
            int row = bm + wm0 + mt * 16 + group;
            int col = bn + wn0 + nt * 8 + tig * 2;
            *(float2*)&g_Y1[(size_t)row * DH + col] = make_float2(d[mt][nt][0], d[mt][nt][1]);
            *(float2*)&g_Y1[(size_t)(row + 8) * DH + col] = make_float2(d[mt][nt][2], d[mt][nt][3]);
        }
    }
}

// ------ fused prop1 + self-loop + bias + relu + @W2 (warp per dst node) ----
__global__ __launch_bounds__(256) void prop1node2_kernel(const float* __restrict__ b1,
                                                         const float* __restrict__ W2) {
    const int node = (blockIdx.x * blockDim.x + threadIdx.x) >> 5;
    const int lane = threadIdx.x & 31;
    if (node >= NNODES) return;
    const int e0 = node << CAPLG;
    const int cnt = g_cnt[node];

    float4 a0 = make_float4(0.f, 0.f, 0.f, 0.f);
    float4 a1 = make_float4(0.f, 0.f, 0.f, 0.f);
    const int fi = 2 * lane;

    int e = 0;
    for (; e + 2 <= cnt; e += 2) {
        int2 edA = __ldg(&g_edge[e0 + e]);
        int2 edB = __ldg(&g_edge[e0 + e + 1]);
        float nA = __int_as_float(edA.y);
        float nB = __int_as_float(edB.y);
        const float4* rA = (const float4*)(g_Y1 + (size_t)edA.x * DH);
        const float4* rB = (const float4*)(g_Y1 + (size_t)edB.x * DH);
        float4 vA0 = __ldg(&rA[fi]),     vB0 = __ldg(&rB[fi]);
        float4 vA1 = __ldg(&rA[fi + 1]), vB1 = __ldg(&rB[fi + 1]);
        a0.x = fmaf(nA, vA0.x, a0.x); a0.y = fmaf(nA, vA0.y, a0.y);
        a0.z = fmaf(nA, vA0.z, a0.z); a0.w = fmaf(nA, vA0.w, a0.w);
        a1.x = fmaf(nA, vA1.x, a1.x); a1.y = fmaf(nA, vA1.y, a1.y);
        a1.z = fmaf(nA, vA1.z, a1.z); a1.w = fmaf(nA, vA1.w, a1.w);
        a0.x = fmaf(nB, vB0.x, a0.x); a0.y = fmaf(nB, vB0.y, a0.y);
        a0.z = fmaf(nB, vB0.z, a0.z); a0.w = fmaf(nB, vB0.w, a0.w);
        a1.x = fmaf(nB, vB1.x, a1.x); a1.y = fmaf(nB, vB1.y, a1.y);
        a1.z = fmaf(nB, vB1.z, a1.z); a1.w = fmaf(nB, vB1.w, a1.w);
    }
    if (e < cnt) {
        int2 edA = __ldg(&g_edge[e0 + e]);
        float nA = __int_as_float(edA.y);
        const float4* rA = (const float4*)(g_Y1 + (size_t)edA.x * DH);
        float4 vA0 = __ldg(&rA[fi]), vA1 = __ldg(&rA[fi + 1]);
        a0.x = fmaf(nA, vA0.x, a0.x); a0.y = fmaf(nA, vA0.y, a0.y);
        a0.z = fmaf(nA, vA0.z, a0.z); a0.w = fmaf(nA, vA0.w, a0.w);
        a1.x = fmaf(nA, vA1.x, a1.x); a1.y = fmaf(nA, vA1.y, a1.y);
        a1.z = fmaf(nA, vA1.z, a1.z); a1.w = fmaf(nA, vA1.w, a1.w);
    }

    float di = g_dinv[node];
    float di2 = di * di;
    const float4* rs = (const float4*)(g_Y1 + (size_t)node * DH);
    float4 s0v = __ldg(&rs[fi]), s1v = __ldg(&rs[fi + 1]);
    a0.x = fmaf(di2, s0v.x, a0.x); a0.y = fmaf(di2, s0v.y, a0.y);
    a0.z = fmaf(di2, s0v.z, a0.z); a0.w = fmaf(di2, s0v.w, a0.w);
    a1.x = fmaf(di2, s1v.x, a1.x); a1.y = fmaf(di2, s1v.y, a1.y);
    a1.z = fmaf(di2, s1v.z, a1.z); a1.w = fmaf(di2, s1v.w, a1.w);

    float4 b0v = __ldg(&((const float4*)b1)[fi]);
    float4 b1v = __ldg(&((const float4*)b1)[fi + 1]);
    float h[8];
    h[0] = fmaxf(a0.x + b0v.x, 0.f); h[1] = fmaxf(a0.y + b0v.y, 0.f);
    h[2] = fmaxf(a0.z + b0v.z, 0.f); h[3] = fmaxf(a0.w + b0v.w, 0.f);
    h[4] = fmaxf(a1.x + b1v.x, 0.f); h[5] = fmaxf(a1.y + b1v.y, 0.f);
    h[6] = fmaxf(a1.z + b1v.z, 0.f); h[7] = fmaxf(a1.w + b1v.w, 0.f);
    float p0 = 0.f, p1 = 0.f;
#pragma unroll
    for (int j = 0; j < 8; ++j) {
        float2 w = __ldg(&((const float2*)W2)[lane * 8 + j]);
        p0 = fmaf(h[j], w.x, p0);
        p1 = fmaf(h[j], w.y, p1);
    }
#pragma unroll
    for (int off = 16; off > 0; off >>= 1) {
        p0 += __shfl_down_sync(0xffffffffu, p0, off);
        p1 += __shfl_down_sync(0xffffffffu, p1, off);
    }
    if (lane == 0) {
        g_Y2[node * 2 + 0] = p0;
        g_Y2[node * 2 + 1] = p1;
    }
}

// ---------------- fused prop2 + finalize (warp per dst node) ---------------
__global__ __launch_bounds__(256) void prop2fin_kernel(const float* __restrict__ b2,
                                                       float* __restrict__ out) {
    const int node = (blockIdx.x * blockDim.x + threadIdx.x) >> 5;
    const int lane = threadIdx.x & 31;
    if (node >= NNODES) return;
    const int e0 = node << CAPLG;
    const int cnt = g_cnt[node];
    float sx = 0.f, sy = 0.f;
    for (int e = lane; e < cnt; e += 32) {
        int2 ed = __ldg(&g_edge[e0 + e]);
        float n = __int_as_float(ed.y);
        float2 y = __ldg(&((const float2*)g_Y2)[ed.x]);
        sx = fmaf(n, y.x, sx);
        sy = fmaf(n, y.y, sy);
    }
#pragma unroll
    for (int off = 16; off > 0; off >>= 1) {
        sx += __shfl_down_sync(0xffffffffu, sx, off);
        sy += __shfl_down_sync(0xffffffffu, sy, off);
    }
    if (lane == 0) {
        float di = g_dinv[node];
        float di2 = di * di;
        float2 y = __ldg(&((const float2*)g_Y2)[node]);
        float ex = sx + y.x * di2 + b2[0];
        float ey = sy + y.y * di2 + b2[1];
        g_ex[node] = ex;
        g_ey[node] = ey;
        out[2 * node + 0] = ex;
        out[2 * node + 1] = ey;
    }
}

// ---------------- q: symmetric upper-triangular 64x64 tiles ----------------
__device__ __forceinline__ float qval(float dx, float dy) {
    float d2 = fmaf(dx, dx, dy * dy);
    float pw = __powf(d2, BETA);
    float q  = __fdividef(1.0f, fmaf(ALPHA, pw, 1.0f));
    return d2 > 0.0f ? q : 1.0f;
}

__global__ __launch_bounds__(256) void q_kernel(float* __restrict__ qout) {
    __shared__ float qs[64][65];
    int b = blockIdx.x;
    int r = (int)((257.0f - sqrtf(66049.0f - 8.0f * (float)b)) * 0.5f);
    while ((r + 1) * 128 - ((r + 1) * r) / 2 <= b) ++r;
    while (r * 128 - (r * (r - 1)) / 2 > b) --r;
    int S = r * 128 - (r * (r - 1)) / 2;
    int bi = r;
    int bj = r + (b - S);
    int ty = threadIdx.x >> 4, tx = threadIdx.x & 15;
    int r0 = ty * 4, c0 = tx * 4;
    bool diag = (bi == bj);

    float4 xj = *(const float4*)&g_ex[bj * 64 + c0];
    float4 yj = *(const float4*)&g_ey[bj * 64 + c0];
#pragma unroll
    for (int u = 0; u < 4; ++u) {
        float xi = g_ex[bi * 64 + r0 + u];
        float yi = g_ey[bi * 64 + r0 + u];
        float4 v;
        v.x = qval(xi - xj.x, yi - yj.x);
        v.y = qval(xi - xj.y, yi - yj.y);
        v.z = qval(xi - xj.z, yi - yj.z);
        v.w = qval(xi - xj.w, yi - yj.w);
        *(float4*)&qout[(size_t)(bi * 64 + r0 + u) * NNODES + bj * 64 + c0] = v;
        if (!diag) {
            qs[r0 + u][c0 + 0] = v.x;
            qs[r0 + u][c0 + 1] = v.y;
            qs[r0 + u][c0 + 2] = v.z;
            qs[r0 + u][c0 + 3] = v.w;
        }
    }
    if (!diag) {
        __syncthreads();
#pragma unroll
        for (int u = 0; u < 4; ++u) {
            float4 v;
            v.x = qs[c0 + 0][r0 + u];
            v.y = qs[c0 + 1][r0 + u];
            v.z = qs[c0 + 2][r0 + u];
            v.w = qs[c0 + 3][r0 + u];
            *(float4*)&qout[(size_t)(bj * 64 + r0 + u) * NNODES + bi * 64 + c0] = v;
        }
    }
}

// ---------------------------------------------------------------------------
extern "C" void kernel_launch(void* const* d_in, const int* in_sizes, int n_in,
                              void* d_out, int out_size) {
    const float* X  = (const float*)d_in[0];
    const int*   ei = (const int*)  d_in[1];
    const float* W1 = (const float*)d_in[2];
    const float* b1 = (const float*)d_in[3];
    const float* W2 = (const float*)d_in[4];
    const float* b2 = (const float*)d_in[5];
    float* out = (float*)d_out;
    (void)in_sizes; (void)n_in; (void)out_size;

    const int* src = ei;
    const int* dst = ei + NEDGES;

    cudaFuncSetAttribute(gemm1_mma_kernel,
                         cudaFuncAttributeMaxDynamicSharedMemorySize, GEMM_SMEM);

    zero_small_kernel<<<NNODES / 256, 256>>>();
    deg_kernel<<<NEDGES / 256, 256>>>(dst);
    dinv_kernel<<<NNODES / 256, 256>>>();
    scatter_kernel<<<NEDGES / 256, 256>>>(src, dst);
    split_kernel<<<NNODES * DIN / 4 / 256, 256>>>(X, W1);
    gemm1_mma_kernel<<<dim3(DH / 64, NNODES / 128), 256, GEMM_SMEM>>>();
    prop1node2_kernel<<<NNODES * 32 / 256, 256>>>(b1, W2);
    prop2fin_kernel<<<NNODES * 32 / 256, 256>>>(b2, out);
    q_kernel<<<128 * 129 / 2, 256>>>(out + NNODES * 2);
}

// round 10
// speedup vs baseline: 1.3656x; 1.0205x over previous
#include <cuda_runtime.h>
#include <cuda_bf16.h>
#include <cstdint>

#define NNODES 8192
#define NEDGES 262144
#define DIN    512
#define DH     256
#define ALPHA  0.1520f
#define BETA   0.7900f
#define CAPLG  7
#define CAP    128   // padded bin capacity per dst node (mean deg = 32, max ~60)

// ---------------- scratch (device globals; no allocation allowed) ----------
__device__ int   g_cur [NNODES];         // doubles as in-degree after scatter
__device__ float g_dinv[NNODES];
__device__ int   g_esrc[NNODES * CAP];   // src index per slot
__device__ __nv_bfloat16 g_Xh [NNODES * DIN];
__device__ __nv_bfloat16 g_Xl [NNODES * DIN];
__device__ __nv_bfloat16 g_W1h[DIN * DH];
__device__ __nv_bfloat16 g_W1l[DIN * DH];
__device__ float g_Y1  [NNODES * DH];   // X @ W1 (fp32)
__device__ float g_Y2  [NNODES * 2];
__device__ float g_ex  [NNODES];
__device__ float g_ey  [NNODES];

// ---------------- zero counters (every replay) -----------------------------
__global__ void zero_small_kernel() {
    int i = blockIdx.x * blockDim.x + threadIdx.x;
    if (i < NNODES) g_cur[i] = 0;
}

// ---------------- scatter edges into padded bins (by dst); counts degree ---
__global__ void scatter_kernel(const int* __restrict__ src, const int* __restrict__ dst) {
    int t = blockIdx.x * blockDim.x + threadIdx.x;   // NEDGES/4 threads
#pragma unroll
    for (int j = 0; j < 4; ++j) {
        int e = t + j * (NEDGES / 4);
        int s = __ldg(&src[e]);
        int d = __ldg(&dst[e]);
        int pos = atomicAdd(&g_cur[d], 1);
        g_esrc[(d << CAPLG) + pos] = s;
    }
}

__global__ void dinv_kernel() {
    int i = blockIdx.x * blockDim.x + threadIdx.x;
    if (i < NNODES) g_dinv[i] = rsqrtf((float)g_cur[i] + 1.0f);
}

// ---------------- bf16 split pre-pass (X and W1 fused) ---------------------
__device__ __forceinline__ void split4(float4 v, uint2* ph, uint2* pl) {
    __nv_bfloat16 h0 = __float2bfloat16_rn(v.x);
    __nv_bfloat16 h1 = __float2bfloat16_rn(v.y);
    __nv_bfloat16 h2 = __float2bfloat16_rn(v.z);
    __nv_bfloat16 h3 = __float2bfloat16_rn(v.w);
    __nv_bfloat16 l0 = __float2bfloat16_rn(v.x - __bfloat162float(h0));
    __nv_bfloat16 l1 = __float2bfloat16_rn(v.y - __bfloat162float(h1));
    __nv_bfloat16 l2 = __float2bfloat16_rn(v.z - __bfloat162float(h2));
    __nv_bfloat16 l3 = __float2bfloat16_rn(v.w - __bfloat162float(h3));
    ph->x = ((uint32_t)__bfloat16_as_ushort(h1) << 16) | __bfloat16_as_ushort(h0);
    ph->y = ((uint32_t)__bfloat16_as_ushort(h3) << 16) | __bfloat16_as_ushort(h2);
    pl->x = ((uint32_t)__bfloat16_as_ushort(l1) << 16) | __bfloat16_as_ushort(l0);
    pl->y = ((uint32_t)__bfloat16_as_ushort(l3) << 16) | __bfloat16_as_ushort(l2);
}

__global__ void split_kernel(const float* __restrict__ X, const float* __restrict__ W1) {
    int i = blockIdx.x * blockDim.x + threadIdx.x;
    if (i < NNODES * DIN / 4) {
        float4 v = __ldg(&((const float4*)X)[i]);
        uint2 ph, pl;
        split4(v, &ph, &pl);
        ((uint2*)g_Xh)[i] = ph;
        ((uint2*)g_Xl)[i] = pl;
    }
    if (i < DIN * DH / 4) {
        float4 v = __ldg(&((const float4*)W1)[i]);
        uint2 ph, pl;
        split4(v, &ph, &pl);
        ((uint2*)g_W1h)[i] = ph;
        ((uint2*)g_W1l)[i] = pl;
    }
}

// ================= GEMM1 via mma.sync bf16 (3-term split) ==================
#define STAGE_BYTES 49152
#define GEMM_SMEM   (2 * STAGE_BYTES)

__device__ __forceinline__ uint32_t smem_u32(const void* p) {
    uint32_t a;
    asm("{ .reg .u64 t; cvta.to.shared.u64 t, %1; cvt.u32.u64 %0, t; }" : "=r"(a) : "l"(p));
    return a;
}
__device__ __forceinline__ void cp16(uint32_t dst, const void* src) {
    asm volatile("cp.async.ca.shared.global [%0], [%1], 16;" :: "r"(dst), "l"(src));
}
__device__ __forceinline__ void ldmatrix_x4(uint32_t* r, uint32_t addr) {
    asm volatile("ldmatrix.sync.aligned.m8n8.x4.shared.b16 {%0,%1,%2,%3}, [%4];"
                 : "=r"(r[0]), "=r"(r[1]), "=r"(r[2]), "=r"(r[3]) : "r"(addr));
}
__device__ __forceinline__ void ldmatrix_x2t(uint32_t* r, uint32_t addr) {
    asm volatile("ldmatrix.sync.aligned.m8n8.x2.trans.shared.b16 {%0,%1}, [%2];"
                 : "=r"(r[0]), "=r"(r[1]) : "r"(addr));
}
__device__ __forceinline__ void mma_bf16(float* d, const uint32_t* a, const uint32_t* b) {
    asm volatile(
        "mma.sync.aligned.m16n8k16.row.col.f32.bf16.bf16.f32 "
        "{%0,%1,%2,%3}, {%4,%5,%6,%7}, {%8,%9}, {%0,%1,%2,%3};"
        : "+f"(d[0]), "+f"(d[1]), "+f"(d[2]), "+f"(d[3])
        : "r"(a[0]), "r"(a[1]), "r"(a[2]), "r"(a[3]), "r"(b[0]), "r"(b[1]));
}

__device__ __forceinline__ void gemm_prefetch(uint32_t sb, int tid, int bm, int bn, int k0) {
#pragma unroll
    for (int p = 0; p < 4; ++p) {
        int idx = tid + p * 256;
        int row = idx >> 3, c16 = idx & 7;
        uint32_t off = (uint32_t)(row * 128 + c16 * 16);
        off ^= (uint32_t)(row & 7) << 4;
        cp16(sb + off,         g_Xh + (size_t)(bm + row) * DIN + k0 + c16 * 8);
        cp16(sb + 16384 + off, g_Xl + (size_t)(bm + row) * DIN + k0 + c16 * 8);
    }
#pragma unroll
    for (int p = 0; p < 2; ++p) {
        int idx = tid + p * 256;
        int row = idx >> 3, c16 = idx & 7;
        uint32_t off = (uint32_t)(row * 128 + c16 * 16);
        off ^= (uint32_t)(row & 7) << 4;
        cp16(sb + 32768 + off, g_W1h + (size_t)(k0 + row) * DH + bn + c16 * 8);
        cp16(sb + 40960 + off, g_W1l + (size_t)(k0 + row) * DH + bn + c16 * 8);
    }
    asm volatile("cp.async.commit_group;");
}

__global__ __launch_bounds__(256) void gemm1_mma_kernel() {
    extern __shared__ __align__(1024) char sm[];
    const uint32_t sbase = smem_u32(sm);
    const int tid = threadIdx.x;
    const int wid = tid >> 5, lane = tid & 31;
    const int bm = blockIdx.y * 128;
    const int bn = blockIdx.x * 64;
    const int wm0 = (wid & 3) * 32;
    const int wn0 = (wid >> 2) * 32;

    float d[2][4][4];
#pragma unroll
    for (int mt = 0; mt < 2; ++mt)
#pragma unroll
        for (int nt = 0; nt < 4; ++nt)
#pragma unroll
            for (int u = 0; u < 4; ++u) d[mt][nt][u] = 0.f;

    gemm_prefetch(sbase, tid, bm, bn, 0);

    for (int ch = 0; ch < 8; ++ch) {
        const uint32_t stb = sbase + (uint32_t)(ch & 1) * STAGE_BYTES;
        if (ch < 7) {
            gemm_prefetch(sbase + (uint32_t)((ch + 1) & 1) * STAGE_BYTES, tid, bm, bn, (ch + 1) * 64);
            asm volatile("cp.async.wait_group 1;");
        } else {
            asm volatile("cp.async.wait_group 0;");
        }
        __syncthreads();

#pragma unroll
        for (int ks = 0; ks < 4; ++ks) {
            const int kk = ks * 16;
            uint32_t ah[2][4], al[2][4], bh[4][2], bl[4][2];
#pragma unroll
            for (int mt = 0; mt < 2; ++mt) {
                int row = wm0 + mt * 16 + (lane & 15);
                uint32_t off = (uint32_t)(row * 128 + kk * 2 + ((lane >> 4) << 4));
                off ^= (uint32_t)(row & 7) << 4;
                ldmatrix_x4(ah[mt], stb + off);
                ldmatrix_x4(al[mt], stb + 16384 + off);
            }
#pragma unroll
            for (int nt = 0; nt < 4; ++nt) {
                int row = kk + (lane & 15);
                uint32_t off = (uint32_t)(row * 128 + (wn0 + nt * 8) * 2);
                off ^= (uint32_t)(row & 7) << 4;
                ldmatrix_x2t(bh[nt], stb + 32768 + off);
                ldmatrix_x2t(bl[nt], stb + 40960 + off);
            }
#pragma unroll
            for (int mt = 0; mt < 2; ++mt)
#pragma unroll
                for (int nt = 0; nt < 4; ++nt) {
                    mma_bf16(d[mt][nt], ah[mt], bh[nt]);
                    mma_bf16(d[mt][nt], ah[mt], bl[nt]);
                    mma_bf16(d[mt][nt], al[mt], bh[nt]);
                }
        }
        __syncthreads();
    }

    const int group = lane >> 2, tig = lane & 3;
#pragma unroll
    for (int mt = 0; mt < 2; ++mt) {
#pragma unroll
        for (int nt = 0; nt < 4; ++nt) {
            int row = bm + wm0 + mt * 16 + group;
            int col = bn + wn0 + nt * 8 + tig * 2;
            *(float2*)&g_Y1[(size_t)row * DH + col] = make_float2(d[mt][nt][0], d[mt][nt][1]);
            *(float2*)&g_Y1[(size_t)(row + 8) * DH + col] = make_float2(d[mt][nt][2], d[mt][nt][3]);
        }
    }
}

// ------ fused prop1 + self-loop + bias + relu + @W2 (warp per dst node) ----
__global__ __launch_bounds__(256) void prop1node2_kernel(const float* __restrict__ b1,
                                                         const float* __restrict__ W2) {
    const int node = (blockIdx.x * blockDim.x + threadIdx.x) >> 5;
    const int lane = threadIdx.x & 31;
    if (node >= NNODES) return;
    const int e0 = node << CAPLG;
    const int cnt = g_cur[node];
    const float di = g_dinv[node];

    float4 a0 = make_float4(0.f, 0.f, 0.f, 0.f);
    float4 a1 = make_float4(0.f, 0.f, 0.f, 0.f);
    const int fi = 2 * lane;

    int e = 0;
    for (; e + 2 <= cnt; e += 2) {
        int sA = __ldg(&g_esrc[e0 + e]);
        int sB = __ldg(&g_esrc[e0 + e + 1]);
        float nA = __ldg(&g_dinv[sA]) * di;
        float nB = __ldg(&g_dinv[sB]) * di;
        const float4* rA = (const float4*)(g_Y1 + (size_t)sA * DH);
        const float4* rB = (const float4*)(g_Y1 + (size_t)sB * DH);
        float4 vA0 = __ldg(&rA[fi]),     vB0 = __ldg(&rB[fi]);
        float4 vA1 = __ldg(&rA[fi + 1]), vB1 = __ldg(&rB[fi + 1]);
        a0.x = fmaf(nA, vA0.x, a0.x); a0.y = fmaf(nA, vA0.y, a0.y);
        a0.z = fmaf(nA, vA0.z, a0.z); a0.w = fmaf(nA, vA0.w, a0.w);
        a1.x = fmaf(nA, vA1.x, a1.x); a1.y = fmaf(nA, vA1.y, a1.y);
        a1.z = fmaf(nA, vA1.z, a1.z); a1.w = fmaf(nA, vA1.w, a1.w);
        a0.x = fmaf(nB, vB0.x, a0.x); a0.y = fmaf(nB, vB0.y, a0.y);
        a0.z = fmaf(nB, vB0.z, a0.z); a0.w = fmaf(nB, vB0.w, a0.w);
        a1.x = fmaf(nB, vB1.x, a1.x); a1.y = fmaf(nB, vB1.y, a1.y);
        a1.z = fmaf(nB, vB1.z, a1.z); a1.w = fmaf(nB, vB1.w, a1.w);
    }
    if (e < cnt) {
        int sA = __ldg(&g_esrc[e0 + e]);
        float nA = __ldg(&g_dinv[sA]) * di;
        const float4* rA = (const float4*)(g_Y1 + (size_t)sA * DH);
        float4 vA0 = __ldg(&rA[fi]), vA1 = __ldg(&rA[fi + 1]);
        a0.x = fmaf(nA, vA0.x, a0.x); a0.y = fmaf(nA, vA0.y, a0.y);
        a0.z = fmaf(nA, vA0.z, a0.z); a0.w = fmaf(nA, vA0.w, a0.w);
        a1.x = fmaf(nA, vA1.x, a1.x); a1.y = fmaf(nA, vA1.y, a1.y);
        a1.z = fmaf(nA, vA1.z, a1.z); a1.w = fmaf(nA, vA1.w, a1.w);
    }

    float di2 = di * di;
    const float4* rs = (const float4*)(g_Y1 + (size_t)node * DH);
    float4 s0v = __ldg(&rs[fi]), s1v = __ldg(&rs[fi + 1]);
    a0.x = fmaf(di2, s0v.x, a0.x); a0.y = fmaf(di2, s0v.y, a0.y);
    a0.z = fmaf(di2, s0v.z, a0.z); a0.w = fmaf(di2, s0v.w, a0.w);
    a1.x = fmaf(di2, s1v.x, a1.x); a1.y = fmaf(di2, s1v.y, a1.y);
    a1.z = fmaf(di2, s1v.z, a1.z); a1.w = fmaf(di2, s1v.w, a1.w);

    float4 b0v = __ldg(&((const float4*)b1)[fi]);
    float4 b1v = __ldg(&((const float4*)b1)[fi + 1]);
    float h[8];
    h[0] = fmaxf(a0.x + b0v.x, 0.f); h[1] = fmaxf(a0.y + b0v.y, 0.f);
    h[2] = fmaxf(a0.z + b0v.z, 0.f); h[3] = fmaxf(a0.w + b0v.w, 0.f);
    h[4] = fmaxf(a1.x + b1v.x, 0.f); h[5] = fmaxf(a1.y + b1v.y, 0.f);
    h[6] = fmaxf(a1.z + b1v.z, 0.f); h[7] = fmaxf(a1.w + b1v.w, 0.f);
    float p0 = 0.f, p1 = 0.f;
#pragma unroll
    for (int j = 0; j < 8; ++j) {
        float2 w = __ldg(&((const float2*)W2)[lane * 8 + j]);
        p0 = fmaf(h[j], w.x, p0);
        p1 = fmaf(h[j], w.y, p1);
    }
#pragma unroll
    for (int off = 16; off > 0; off >>= 1) {
        p0 += __shfl_down_sync(0xffffffffu, p0, off);
        p1 += __shfl_down_sync(0xffffffffu, p1, off);
    }
    if (lane == 0) {
        g_Y2[node * 2 + 0] = p0;
        g_Y2[node * 2 + 1] = p1;
    }
}

// ---------------- fused prop2 + finalize (warp per dst node) ---------------
__global__ __launch_bounds__(256) void prop2fin_kernel(const float* __restrict__ b2,
                                                       float* __restrict__ out) {
    const int node = (blockIdx.x * blockDim.x + threadIdx.x) >> 5;
    const int lane = threadIdx.x & 31;
    if (node >= NNODES) return;
    const int e0 = node << CAPLG;
    const int cnt = g_cur[node];
    const float di = g_dinv[node];
    float sx = 0.f, sy = 0.f;
    for (int e = lane; e < cnt; e += 32) {
        int s = __ldg(&g_esrc[e0 + e]);
        float n = __ldg(&g_dinv[s]) * di;
        float2 y = __ldg(&((const float2*)g_Y2)[s]);
        sx = fmaf(n, y.x, sx);
        sy = fmaf(n, y.y, sy);
    }
#pragma unroll
    for (int off = 16; off > 0; off >>= 1) {
        sx += __shfl_down_sync(0xffffffffu, sx, off);
        sy += __shfl_down_sync(0xffffffffu, sy, off);
    }
    if (lane == 0) {
        float di2 = di * di;
        float2 y = __ldg(&((const float2*)g_Y2)[node]);
        float ex = sx + y.x * di2 + b2[0];
        float ey = sy + y.y * di2 + b2[1];
        g_ex[node] = ex;
        g_ey[node] = ey;
        out[2 * node + 0] = ex;
        out[2 * node + 1] = ey;
    }
}

// ---------------- q: symmetric upper-triangular 64x64 tiles ----------------
__device__ __forceinline__ float qval(float dx, float dy) {
    float d2 = fmaf(dx, dx, dy * dy);
    float pw = __powf(d2, BETA);
    float q  = __fdividef(1.0f, fmaf(ALPHA, pw, 1.0f));
    return d2 > 0.0f ? q : 1.0f;
}

__global__ __launch_bounds__(256) void q_kernel(float* __restrict__ qout) {
    __shared__ float qs[64][65];
    int b = blockIdx.x;
    int r = (int)((257.0f - sqrtf(66049.0f - 8.0f * (float)b)) * 0.5f);
    while ((r + 1) * 128 - ((r + 1) * r) / 2 <= b) ++r;
    while (r * 128 - (r * (r - 1)) / 2 > b) --r;
    int S = r * 128 - (r * (r - 1)) / 2;
    int bi = r;
    int bj = r + (b - S);
    int ty = threadIdx.x >> 4, tx = threadIdx.x & 15;
    int r0 = ty * 4, c0 = tx * 4;
    bool diag = (bi == bj);

    float4 xj = *(const float4*)&g_ex[bj * 64 + c0];
    float4 yj = *(const float4*)&g_ey[bj * 64 + c0];
#pragma unroll
    for (int u = 0; u < 4; ++u) {
        float xi = g_ex[bi * 64 + r0 + u];
        float yi = g_ey[bi * 64 + r0 + u];
        float4 v;
        v.x = qval(xi - xj.x, yi - yj.x);
        v.y = qval(xi - xj.y, yi - yj.y);
        v.z = qval(xi - xj.z, yi - yj.z);
        v.w = qval(xi - xj.w, yi - yj.w);
        *(float4*)&qout[(size_t)(bi * 64 + r0 + u) * NNODES + bj * 64 + c0] = v;
        if (!diag) {
            qs[r0 + u][c0 + 0] = v.x;
            qs[r0 + u][c0 + 1] = v.y;
            qs[r0 + u][c0 + 2] = v.z;
            qs[r0 + u][c0 + 3] = v.w;
        }
    }
    if (!diag) {
        __syncthreads();
#pragma unroll
        for (int u = 0; u < 4; ++u) {
            float4 v;
            v.x = qs[c0 + 0][r0 + u];
            v.y = qs[c0 + 1][r0 + u];
            v.z = qs[c0 + 2][r0 + u];
            v.w = qs[c0 + 3][r0 + u];
            *(float4*)&qout[(size_t)(bj * 64 + r0 + u) * NNODES + bi * 64 + c0] = v;
        }
    }
}

// ---------------------------------------------------------------------------
extern "C" void kernel_launch(void* const* d_in, const int* in_sizes, int n_in,
                              void* d_out, int out_size) {
    const float* X  = (const float*)d_in[0];
    const int*   ei = (const int*)  d_in[1];
    const float* W1 = (const float*)d_in[2];
    const float* b1 = (const float*)d_in[3];
    const float* W2 = (const float*)d_in[4];
    const float* b2 = (const float*)d_in[5];
    float* out = (float*)d_out;
    (void)in_sizes; (void)n_in; (void)out_size;

    const int* src = ei;
    const int* dst = ei + NEDGES;

    cudaFuncSetAttribute(gemm1_mma_kernel,
                         cudaFuncAttributeMaxDynamicSharedMemorySize, GEMM_SMEM);

    zero_small_kernel<<<NNODES / 256, 256>>>();
    scatter_kernel<<<NEDGES / 4 / 256, 256>>>(src, dst);
    dinv_kernel<<<NNODES / 256, 256>>>();
    split_kernel<<<NNODES * DIN / 4 / 256, 256>>>(X, W1);
    gemm1_mma_kernel<<<dim3(DH / 64, NNODES / 128), 256, GEMM_SMEM>>>();
    prop1node2_kernel<<<NNODES * 32 / 256, 256>>>(b1, W2);
    prop2fin_kernel<<<NNODES * 32 / 256, 256>>>(b2, out);
    q_kernel<<<128 * 129 / 2, 256>>>(out + NNODES * 2);
}

// round 11
// speedup vs baseline: 1.4332x; 1.0495x over previous
#include <cuda_runtime.h>
#include <cuda_bf16.h>
#include <cstdint>

#define NNODES 8192
#define NEDGES 262144
#define DIN    512
#define DH     256
#define ALPHA  0.1520f
#define BETA   0.7900f
#define CAPLG  7
#define CAP    128   // padded bin capacity per dst node (mean deg = 32, max ~60)

// ---------------- scratch (device globals; no allocation allowed) ----------
__device__ int   g_cur [NNODES];         // doubles as in-degree after scatter
__device__ float g_dinv[NNODES];
__device__ int   g_esrc[NNODES * CAP];   // src index per slot
__device__ __nv_bfloat16 g_Xh [NNODES * DIN];
__device__ __nv_bfloat16 g_Xl [NNODES * DIN];
__device__ __nv_bfloat16 g_W1h[DIN * DH];
__device__ __nv_bfloat16 g_W1l[DIN * DH];
__device__ float g_Y1  [NNODES * DH];   // X @ W1 (fp32)
__device__ float g_Y2  [NNODES * 2];
__device__ float g_ex  [NNODES];
__device__ float g_ey  [NNODES];

// ---------------- zero counters (every replay) -----------------------------
__global__ void zero_small_kernel() {
    int i = blockIdx.x * blockDim.x + threadIdx.x;
    if (i < NNODES) g_cur[i] = 0;
}

// ---------------- scatter edges into padded bins (by dst); counts degree ---
__global__ void scatter_kernel(const int* __restrict__ src, const int* __restrict__ dst) {
    int t = blockIdx.x * blockDim.x + threadIdx.x;   // NEDGES/4 threads
#pragma unroll
    for (int j = 0; j < 4; ++j) {
        int e = t + j * (NEDGES / 4);
        int s = __ldg(&src[e]);
        int d = __ldg(&dst[e]);
        int pos = atomicAdd(&g_cur[d], 1);
        g_esrc[(d << CAPLG) + pos] = s;
    }
}

__global__ void dinv_kernel() {
    int i = blockIdx.x * blockDim.x + threadIdx.x;
    if (i < NNODES) g_dinv[i] = rsqrtf((float)g_cur[i] + 1.0f);
}

// ---------------- bf16 split pre-pass (X and W1 fused) ---------------------
__device__ __forceinline__ void split4(float4 v, uint2* ph, uint2* pl) {
    __nv_bfloat16 h0 = __float2bfloat16_rn(v.x);
    __nv_bfloat16 h1 = __float2bfloat16_rn(v.y);
    __nv_bfloat16 h2 = __float2bfloat16_rn(v.z);
    __nv_bfloat16 h3 = __float2bfloat16_rn(v.w);
    __nv_bfloat16 l0 = __float2bfloat16_rn(v.x - __bfloat162float(h0));
    __nv_bfloat16 l1 = __float2bfloat16_rn(v.y - __bfloat162float(h1));
    __nv_bfloat16 l2 = __float2bfloat16_rn(v.z - __bfloat162float(h2));
    __nv_bfloat16 l3 = __float2bfloat16_rn(v.w - __bfloat162float(h3));
    ph->x = ((uint32_t)__bfloat16_as_ushort(h1) << 16) | __bfloat16_as_ushort(h0);
    ph->y = ((uint32_t)__bfloat16_as_ushort(h3) << 16) | __bfloat16_as_ushort(h2);
    pl->x = ((uint32_t)__bfloat16_as_ushort(l1) << 16) | __bfloat16_as_ushort(l0);
    pl->y = ((uint32_t)__bfloat16_as_ushort(l3) << 16) | __bfloat16_as_ushort(l2);
}

__global__ void split_kernel(const float* __restrict__ X, const float* __restrict__ W1) {
    int i = blockIdx.x * blockDim.x + threadIdx.x;   // NNODES*DIN/8 threads
    const int HALF = NNODES * DIN / 8;
#pragma unroll
    for (int j = 0; j < 2; ++j) {
        int idx = i + j * HALF;
        float4 v = __ldg(&((const float4*)X)[idx]);
        uint2 ph, pl;
        split4(v, &ph, &pl);
        ((uint2*)g_Xh)[idx] = ph;
        ((uint2*)g_Xl)[idx] = pl;
    }
    if (i < DIN * DH / 4) {
        float4 v = __ldg(&((const float4*)W1)[i]);
        uint2 ph, pl;
        split4(v, &ph, &pl);
        ((uint2*)g_W1h)[i] = ph;
        ((uint2*)g_W1l)[i] = pl;
    }
}

// ================= GEMM1 via mma.sync bf16 (3-term split) ==================
// CTA tile 128(m) x 64(n); K in 16 chunks of 32; 4-stage cp.async pipeline.
// Stage: Ah 8KB | Al 8KB | Bh 4KB | Bl 4KB = 24KB; 4 stages = 96KB (2 CTA/SM).

#define CHUNK_K     32
#define NCHUNKS     (DIN / CHUNK_K)      // 16
#define STAGE_BYTES 24576
#define NSTAGES     4
#define GEMM_SMEM   (NSTAGES * STAGE_BYTES)

__device__ __forceinline__ uint32_t smem_u32(const void* p) {
    uint32_t a;
    asm("{ .reg .u64 t; cvta.to.shared.u64 t, %1; cvt.u32.u64 %0, t; }" : "=r"(a) : "l"(p));
    return a;
}
__device__ __forceinline__ void cp16(uint32_t dst, const void* src) {
    asm volatile("cp.async.cg.shared.global [%0], [%1], 16;" :: "r"(dst), "l"(src));
}
__device__ __forceinline__ void ldmatrix_x4(uint32_t* r, uint32_t addr) {
    asm volatile("ldmatrix.sync.aligned.m8n8.x4.shared.b16 {%0,%1,%2,%3}, [%4];"
                 : "=r"(r[0]), "=r"(r[1]), "=r"(r[2]), "=r"(r[3]) : "r"(addr));
}
__device__ __forceinline__ void ldmatrix_x2t(uint32_t* r, uint32_t addr) {
    asm volatile("ldmatrix.sync.aligned.m8n8.x2.trans.shared.b16 {%0,%1}, [%2];"
                 : "=r"(r[0]), "=r"(r[1]) : "r"(addr));
}
__device__ __forceinline__ void mma_bf16(float* d, const uint32_t* a, const uint32_t* b) {
    asm volatile(
        "mma.sync.aligned.m16n8k16.row.col.f32.bf16.bf16.f32 "
        "{%0,%1,%2,%3}, {%4,%5,%6,%7}, {%8,%9}, {%0,%1,%2,%3};"
        : "+f"(d[0]), "+f"(d[1]), "+f"(d[2]), "+f"(d[3])
        : "r"(a[0]), "r"(a[1]), "r"(a[2]), "r"(a[3]), "r"(b[0]), "r"(b[1]));
}

// Prefetch one K=32 chunk into stage at smem offset sb.
// A rows: 64B (32 k * 2B), swizzle c16 ^= row&3. B rows: 128B, swizzle ^(row&7).
__device__ __forceinline__ void gemm_prefetch(uint32_t sb, int tid, int bm, int bn, int k0) {
#pragma unroll
    for (int p = 0; p < 2; ++p) {
        int idx = tid + p * 256;
        int row = idx >> 2, c16 = idx & 3;
        uint32_t off = (uint32_t)(row * 64 + c16 * 16);
        off ^= (uint32_t)(row & 3) << 4;
        cp16(sb + off,        g_Xh + (size_t)(bm + row) * DIN + k0 + c16 * 8);
        cp16(sb + 8192 + off, g_Xl + (size_t)(bm + row) * DIN + k0 + c16 * 8);
    }
    {
        int row = tid >> 3, c16 = tid & 7;
        uint32_t off = (uint32_t)(row * 128 + c16 * 16);
        off ^= (uint32_t)(row & 7) << 4;
        cp16(sb + 16384 + off, g_W1h + (size_t)(k0 + row) * DH + bn + c16 * 8);
        cp16(sb + 20480 + off, g_W1l + (size_t)(k0 + row) * DH + bn + c16 * 8);
    }
}

__global__ __launch_bounds__(256) void gemm1_mma_kernel() {
    extern __shared__ __align__(1024) char sm[];
    const uint32_t sbase = smem_u32(sm);
    const int tid = threadIdx.x;
    const int wid = tid >> 5, lane = tid & 31;
    const int bm = blockIdx.y * 128;
    const int bn = blockIdx.x * 64;
    const int wm0 = (wid & 3) * 32;
    const int wn0 = (wid >> 2) * 32;

    float d[2][4][4];
#pragma unroll
    for (int mt = 0; mt < 2; ++mt)
#pragma unroll
        for (int nt = 0; nt < 4; ++nt)
#pragma unroll
            for (int u = 0; u < 4; ++u) d[mt][nt][u] = 0.f;

    // prologue: stages 0..2 in flight
#pragma unroll
    for (int c = 0; c < NSTAGES - 1; ++c) {
        gemm_prefetch(sbase + (uint32_t)c * STAGE_BYTES, tid, bm, bn, c * CHUNK_K);
        asm volatile("cp.async.commit_group;");
    }

    for (int ch = 0; ch < NCHUNKS; ++ch) {
        asm volatile("cp.async.wait_group %0;" :: "n"(NSTAGES - 2));
        __syncthreads();
        const uint32_t stb = sbase + (uint32_t)(ch & (NSTAGES - 1)) * STAGE_BYTES;

#pragma unroll
        for (int ks = 0; ks < 2; ++ks) {
            const int kk = ks * 16;
            uint32_t ah[2][4], al[2][4], bh[4][2], bl[4][2];
#pragma unroll
            for (int mt = 0; mt < 2; ++mt) {
                int row = wm0 + mt * 16 + (lane & 15);
                uint32_t off = (uint32_t)(row * 64 + kk * 2 + ((lane >> 4) << 4));
                off ^= (uint32_t)(row & 3) << 4;
                ldmatrix_x4(ah[mt], stb + off);
                ldmatrix_x4(al[mt], stb + 8192 + off);
            }
#pragma unroll
            for (int nt = 0; nt < 4; ++nt) {
                int row = kk + (lane & 15);
                uint32_t off = (uint32_t)(row * 128 + (wn0 + nt * 8) * 2);
                off ^= (uint32_t)(row & 7) << 4;
                ldmatrix_x2t(bh[nt], stb + 16384 + off);
                ldmatrix_x2t(bl[nt], stb + 20480 + off);
            }
#pragma unroll
            for (int mt = 0; mt < 2; ++mt)
#pragma unroll
                for (int nt = 0; nt < 4; ++nt) {
                    mma_bf16(d[mt][nt], ah[mt], bh[nt]);
                    mma_bf16(d[mt][nt], ah[mt], bl[nt]);
                    mma_bf16(d[mt][nt], al[mt], bh[nt]);
                }
        }

        // prefetch chunk ch+3 into the stage freed by chunk ch-1 (safe: all
        // warps passed this iteration's sync => finished compute of ch-1).
        if (ch + NSTAGES - 1 < NCHUNKS) {
            gemm_prefetch(sbase + (uint32_t)((ch + NSTAGES - 1) & (NSTAGES - 1)) * STAGE_BYTES,
                          tid, bm, bn, (ch + NSTAGES - 1) * CHUNK_K);
        }
        asm volatile("cp.async.commit_group;");   // empty group at tail keeps FIFO uniform
    }

    const int group = lane >> 2, tig = lane & 3;
#pragma unroll
    for (int mt = 0; mt < 2; ++mt) {
#pragma unroll
        for (int nt = 0; nt < 4; ++nt) {
            int row = bm + wm0 + mt * 16 + group;
            int col = bn + wn0 + nt * 8 + tig * 2;
            *(float2*)&g_Y1[(size_t)row * DH + col] = make_float2(d[mt][nt][0], d[mt][nt][1]);
            *(float2*)&g_Y1[(size_t)(row + 8) * DH + col] = make_float2(d[mt][nt][2], d[mt][nt][3]);
        }
    }
}

// ------ fused prop1 + self-loop + bias + relu + @W2 (warp per dst node) ----
__global__ __launch_bounds__(256) void prop1node2_kernel(const float* __restrict__ b1,
                                                         const float* __restrict__ W2) {
    const int node = (blockIdx.x * blockDim.x + threadIdx.x) >> 5;
    const int lane = threadIdx.x & 31;
    if (node >= NNODES) return;
    const int e0 = node << CAPLG;
    const int cnt = g_cur[node];
    const float di = g_dinv[node];

    float4 a0 = make_float4(0.f, 0.f, 0.f, 0.f);
    float4 a1 = make_float4(0.f, 0.f, 0.f, 0.f);
    const int fi = 2 * lane;

    int e = 0;
    for (; e + 2 <= cnt; e += 2) {
        int sA = __ldg(&g_esrc[e0 + e]);
        int sB = __ldg(&g_esrc[e0 + e + 1]);
        float nA = __ldg(&g_dinv[sA]) * di;
        float nB = __ldg(&g_dinv[sB]) * di;
        const float4* rA = (const float4*)(g_Y1 + (size_t)sA * DH);
        const float4* rB = (const float4*)(g_Y1 + (size_t)sB * DH);
        float4 vA0 = __ldg(&rA[fi]),     vB0 = __ldg(&rB[fi]);
        float4 vA1 = __ldg(&rA[fi + 1]), vB1 = __ldg(&rB[fi + 1]);
        a0.x = fmaf(nA, vA0.x, a0.x); a0.y = fmaf(nA, vA0.y, a0.y);
        a0.z = fmaf(nA, vA0.z, a0.z); a0.w = fmaf(nA, vA0.w, a0.w);
        a1.x = fmaf(nA, vA1.x, a1.x); a1.y = fmaf(nA, vA1.y, a1.y);
        a1.z = fmaf(nA, vA1.z, a1.z); a1.w = fmaf(nA, vA1.w, a1.w);
        a0.x = fmaf(nB, vB0.x, a0.x); a0.y = fmaf(nB, vB0.y, a0.y);
        a0.z = fmaf(nB, vB0.z, a0.z); a0.w = fmaf(nB, vB0.w, a0.w);
        a1.x = fmaf(nB, vB1.x, a1.x); a1.y = fmaf(nB, vB1.y, a1.y);
        a1.z = fmaf(nB, vB1.z, a1.z); a1.w = fmaf(nB, vB1.w, a1.w);
    }
    if (e < cnt) {
        int sA = __ldg(&g_esrc[e0 + e]);
        float nA = __ldg(&g_dinv[sA]) * di;
        const float4* rA = (const float4*)(g_Y1 + (size_t)sA * DH);
        float4 vA0 = __ldg(&rA[fi]), vA1 = __ldg(&rA[fi + 1]);
        a0.x = fmaf(nA, vA0.x, a0.x); a0.y = fmaf(nA, vA0.y, a0.y);
        a0.z = fmaf(nA, vA0.z, a0.z); a0.w = fmaf(nA, vA0.w, a0.w);
        a1.x = fmaf(nA, vA1.x, a1.x); a1.y = fmaf(nA, vA1.y, a1.y);
        a1.z = fmaf(nA, vA1.z, a1.z); a1.w = fmaf(nA, vA1.w, a1.w);
    }

    float di2 = di * di;
    const float4* rs = (const float4*)(g_Y1 + (size_t)node * DH);
    float4 s0v = __ldg(&rs[fi]), s1v = __ldg(&rs[fi + 1]);
    a0.x = fmaf(di2, s0v.x, a0.x); a0.y = fmaf(di2, s0v.y, a0.y);
    a0.z = fmaf(di2, s0v.z, a0.z); a0.w = fmaf(di2, s0v.w, a0.w);
    a1.x = fmaf(di2, s1v.x, a1.x); a1.y = fmaf(di2, s1v.y, a1.y);
    a1.z = fmaf(di2, s1v.z, a1.z); a1.w = fmaf(di2, s1v.w, a1.w);

    float4 b0v = __ldg(&((const float4*)b1)[fi]);
    float4 b1v = __ldg(&((const float4*)b1)[fi + 1]);
    float h[8];
    h[0] = fmaxf(a0.x + b0v.x, 0.f); h[1] = fmaxf(a0.y + b0v.y, 0.f);
    h[2] = fmaxf(a0.z + b0v.z, 0.f); h[3] = fmaxf(a0.w + b0v.w, 0.f);
    h[4] = fmaxf(a1.x + b1v.x, 0.f); h[5] = fmaxf(a1.y + b1v.y, 0.f);
    h[6] = fmaxf(a1.z + b1v.z, 0.f); h[7] = fmaxf(a1.w + b1v.w, 0.f);
    float p0 = 0.f, p1 = 0.f;
#pragma unroll
    for (int j = 0; j < 8; ++j) {
        float2 w = __ldg(&((const float2*)W2)[lane * 8 + j]);
        p0 = fmaf(h[j], w.x, p0);
        p1 = fmaf(h[j], w.y, p1);
    }
#pragma unroll
    for (int off = 16; off > 0; off >>= 1) {
        p0 += __shfl_down_sync(0xffffffffu, p0, off);
        p1 += __shfl_down_sync(0xffffffffu, p1, off);
    }
    if (lane == 0) {
        g_Y2[node * 2 + 0] = p0;
        g_Y2[node * 2 + 1] = p1;
    }
}

// ---------------- fused prop2 + finalize (warp per dst node) ---------------
__global__ __launch_bounds__(256) void prop2fin_kernel(const float* __restrict__ b2,
                                                       float* __restrict__ out) {
    const int node = (blockIdx.x * blockDim.x + threadIdx.x) >> 5;
    const int lane = threadIdx.x & 31;
    if (node >= NNODES) return;
    const int e0 = node << CAPLG;
    const int cnt = g_cur[node];
    const float di = g_dinv[node];
    float sx = 0.f, sy = 0.f;
    for (int e = lane; e < cnt; e += 32) {
        int s = __ldg(&g_esrc[e0 + e]);
        float n = __ldg(&g_dinv[s]) * di;
        float2 y = __ldg(&((const float2*)g_Y2)[s]);
        sx = fmaf(n, y.x, sx);
        sy = fmaf(n, y.y, sy);
    }
#pragma unroll
    for (int off = 16; off > 0; off >>= 1) {
        sx += __shfl_down_sync(0xffffffffu, sx, off);
        sy += __shfl_down_sync(0xffffffffu, sy, off);
    }
    if (lane == 0) {
        float di2 = di * di;
        float2 y = __ldg(&((const float2*)g_Y2)[node]);
        float ex = sx + y.x * di2 + b2[0];
        float ey = sy + y.y * di2 + b2[1];
        g_ex[node] = ex;
        g_ey[node] = ey;
        out[2 * node + 0] = ex;
        out[2 * node + 1] = ey;
    }
}

// ---------------- q: symmetric upper-triangular 64x64 tiles ----------------
__device__ __forceinline__ float qval(float dx, float dy) {
    float d2 = fmaf(dx, dx, dy * dy);
    float pw = __powf(d2, BETA);
    float q  = __fdividef(1.0f, fmaf(ALPHA, pw, 1.0f));
    return d2 > 0.0f ? q : 1.0f;
}

__global__ __launch_bounds__(256) void q_kernel(float* __restrict__ qout) {
    __shared__ float qs[64][65];
    int b = blockIdx.x;
    int r = (int)((257.0f - sqrtf(66049.0f - 8.0f * (float)b)) * 0.5f);
    while ((r + 1) * 128 - ((r + 1) * r) / 2 <= b) ++r;
    while (r * 128 - (r * (r - 1)) / 2 > b) --r;
    int S = r * 128 - (r * (r - 1)) / 2;
    int bi = r;
    int bj = r + (b - S);
    int ty = threadIdx.x >> 4, tx = threadIdx.x & 15;
    int r0 = ty * 4, c0 = tx * 4;
    bool diag = (bi == bj);

    float4 xj = *(const float4*)&g_ex[bj * 64 + c0];
    float4 yj = *(const float4*)&g_ey[bj * 64 + c0];
#pragma unroll
    for (int u = 0; u < 4; ++u) {
        float xi = g_ex[bi * 64 + r0 + u];
        float yi = g_ey[bi * 64 + r0 + u];
        float4 v;
        v.x = qval(xi - xj.x, yi - yj.x);
        v.y = qval(xi - xj.y, yi - yj.y);
        v.z = qval(xi - xj.z, yi - yj.z);
        v.w = qval(xi - xj.w, yi - yj.w);
        __stcs((float4*)&qout[(size_t)(bi * 64 + r0 + u) * NNODES + bj * 64 + c0], v);
        if (!diag) {
            qs[r0 + u][c0 + 0] = v.x;
            qs[r0 + u][c0 + 1] = v.y;
            qs[r0 + u][c0 + 2] = v.z;
            qs[r0 + u][c0 + 3] = v.w;
        }
    }
    if (!diag) {
        __syncthreads();
#pragma unroll
        for (int u = 0; u < 4; ++u) {
            float4 v;
            v.x = qs[c0 + 0][r0 + u];
            v.y = qs[c0 + 1][r0 + u];
            v.z = qs[c0 + 2][r0 + u];
            v.w = qs[c0 + 3][r0 + u];
            __stcs((float4*)&qout[(size_t)(bj * 64 + r0 + u) * NNODES + bi * 64 + c0], v);
        }
    }
}

// ---------------------------------------------------------------------------
extern "C" void kernel_launch(void* const* d_in, const int* in_sizes, int n_in,
                              void* d_out, int out_size) {
    const float* X  = (const float*)d_in[0];
    const int*   ei = (const int*)  d_in[1];
    const float* W1 = (const float*)d_in[2];
    const float* b1 = (const float*)d_in[3];
    const float* W2 = (const float*)d_in[4];
    const float* b2 = (const float*)d_in[5];
    float* out = (float*)d_out;
    (void)in_sizes; (void)n_in; (void)out_size;

    const int* src = ei;
    const int* dst = ei + NEDGES;

    cudaFuncSetAttribute(gemm1_mma_kernel,
                         cudaFuncAttributeMaxDynamicSharedMemorySize, GEMM_SMEM);

    zero_small_kernel<<<NNODES / 256, 256>>>();
    scatter_kernel<<<NEDGES / 4 / 256, 256>>>(src, dst);
    dinv_kernel<<<NNODES / 256, 256>>>();
    split_kernel<<<NNODES * DIN / 8 / 256, 256>>>(X, W1);
    gemm1_mma_kernel<<<dim3(DH / 64, NNODES / 128), 256, GEMM_SMEM>>>();
    prop1node2_kernel<<<NNODES * 32 / 256, 256>>>(b1, W2);
    prop2fin_kernel<<<NNODES * 32 / 256, 256>>>(b2, out);
    q_kernel<<<128 * 129 / 2, 256>>>(out + NNODES * 2);
}

// round 12
// speedup vs baseline: 1.6619x; 1.1595x over previous
#include <cuda_runtime.h>
#include <cuda_fp16.h>
#include <cuda_bf16.h>
#include <cstdint>

#define NNODES 8192
#define NEDGES 262144
#define DIN    512
#define DH     256
#define ALPHA  0.1520f
#define BETA   0.7900f
#define CAPLG  7
#define CAP    128   // padded bin capacity per dst node (mean deg = 32, max ~60)

// ---------------- scratch (device globals; no allocation allowed) ----------
__device__ int   g_cur [NNODES];         // doubles as in-degree after scatter
__device__ float g_dinv[NNODES];
__device__ int   g_esrc[NNODES * CAP];   // src index per slot
__device__ __nv_bfloat16 g_Xh [NNODES * DIN];
__device__ __nv_bfloat16 g_Xl [NNODES * DIN];
__device__ __nv_bfloat16 g_W1h[DIN * DH];
__device__ __nv_bfloat16 g_W1l[DIN * DH];
__device__ __half g_Y1h[NNODES * DH];   // X @ W1 (fp16, sole copy)
__device__ float g_Y2  [NNODES * 2];
__device__ float g_ex  [NNODES];
__device__ float g_ey  [NNODES];

// ---------------- zero counters (every replay) -----------------------------
__global__ void zero_small_kernel() {
    int i = blockIdx.x * blockDim.x + threadIdx.x;
    if (i < NNODES) g_cur[i] = 0;
}

// ---------------- scatter edges into padded bins (by dst); counts degree ---
__global__ void scatter_kernel(const int* __restrict__ src, const int* __restrict__ dst) {
    int t = blockIdx.x * blockDim.x + threadIdx.x;   // NEDGES/4 threads
#pragma unroll
    for (int j = 0; j < 4; ++j) {
        int e = t + j * (NEDGES / 4);
        int s = __ldg(&src[e]);
        int d = __ldg(&dst[e]);
        int pos = atomicAdd(&g_cur[d], 1);
        g_esrc[(d << CAPLG) + pos] = s;
    }
}

__global__ void dinv_kernel() {
    int i = blockIdx.x * blockDim.x + threadIdx.x;
    if (i < NNODES) g_dinv[i] = rsqrtf((float)g_cur[i] + 1.0f);
}

// ---------------- bf16 split pre-pass (X and W1 fused) ---------------------
__device__ __forceinline__ void split4(float4 v, uint2* ph, uint2* pl) {
    __nv_bfloat16 h0 = __float2bfloat16_rn(v.x);
    __nv_bfloat16 h1 = __float2bfloat16_rn(v.y);
    __nv_bfloat16 h2 = __float2bfloat16_rn(v.z);
    __nv_bfloat16 h3 = __float2bfloat16_rn(v.w);
    __nv_bfloat16 l0 = __float2bfloat16_rn(v.x - __bfloat162float(h0));
    __nv_bfloat16 l1 = __float2bfloat16_rn(v.y - __bfloat162float(h1));
    __nv_bfloat16 l2 = __float2bfloat16_rn(v.z - __bfloat162float(h2));
    __nv_bfloat16 l3 = __float2bfloat16_rn(v.w - __bfloat162float(h3));
    ph->x = ((uint32_t)__bfloat16_as_ushort(h1) << 16) | __bfloat16_as_ushort(h0);
    ph->y = ((uint32_t)__bfloat16_as_ushort(h3) << 16) | __bfloat16_as_ushort(h2);
    pl->x = ((uint32_t)__bfloat16_as_ushort(l1) << 16) | __bfloat16_as_ushort(l0);
    pl->y = ((uint32_t)__bfloat16_as_ushort(l3) << 16) | __bfloat16_as_ushort(l2);
}

__global__ void split_kernel(const float* __restrict__ X, const float* __restrict__ W1) {
    int i = blockIdx.x * blockDim.x + threadIdx.x;   // NNODES*DIN/8 threads
    const int HALF = NNODES * DIN / 8;
#pragma unroll
    for (int j = 0; j < 2; ++j) {
        int idx = i + j * HALF;
        float4 v = __ldg(&((const float4*)X)[idx]);
        uint2 ph, pl;
        split4(v, &ph, &pl);
        ((uint2*)g_Xh)[idx] = ph;
        ((uint2*)g_Xl)[idx] = pl;
    }
    if (i < DIN * DH / 4) {
        float4 v = __ldg(&((const float4*)W1)[i]);
        uint2 ph, pl;
        split4(v, &ph, &pl);
        ((uint2*)g_W1h)[i] = ph;
        ((uint2*)g_W1l)[i] = pl;
    }
}

// ================= GEMM1 via mma.sync bf16 (3-term split) ==================
// CTA tile 128(m) x 64(n); K in 16 chunks of 32; 4-stage cp.async pipeline.
// Stage: Ah 8KB | Al 8KB | Bh 4KB | Bl 4KB = 24KB; 4 stages = 96KB (2 CTA/SM).

#define CHUNK_K     32
#define NCHUNKS     (DIN / CHUNK_K)      // 16
#define STAGE_BYTES 24576
#define NSTAGES     4
#define GEMM_SMEM   (NSTAGES * STAGE_BYTES)

__device__ __forceinline__ uint32_t smem_u32(const void* p) {
    uint32_t a;
    asm("{ .reg .u64 t; cvta.to.shared.u64 t, %1; cvt.u32.u64 %0, t; }" : "=r"(a) : "l"(p));
    return a;
}
__device__ __forceinline__ void cp16(uint32_t dst, const void* src) {
    asm volatile("cp.async.cg.shared.global [%0], [%1], 16;" :: "r"(dst), "l"(src));
}
__device__ __forceinline__ void ldmatrix_x4(uint32_t* r, uint32_t addr) {
    asm volatile("ldmatrix.sync.aligned.m8n8.x4.shared.b16 {%0,%1,%2,%3}, [%4];"
                 : "=r"(r[0]), "=r"(r[1]), "=r"(r[2]), "=r"(r[3]) : "r"(addr));
}
__device__ __forceinline__ void ldmatrix_x2t(uint32_t* r, uint32_t addr) {
    asm volatile("ldmatrix.sync.aligned.m8n8.x2.trans.shared.b16 {%0,%1}, [%2];"
                 : "=r"(r[0]), "=r"(r[1]) : "r"(addr));
}
__device__ __forceinline__ void mma_bf16(float* d, const uint32_t* a, const uint32_t* b) {
    asm volatile(
        "mma.sync.aligned.m16n8k16.row.col.f32.bf16.bf16.f32 "
        "{%0,%1,%2,%3}, {%4,%5,%6,%7}, {%8,%9}, {%0,%1,%2,%3};"
        : "+f"(d[0]), "+f"(d[1]), "+f"(d[2]), "+f"(d[3])
        : "r"(a[0]), "r"(a[1]), "r"(a[2]), "r"(a[3]), "r"(b[0]), "r"(b[1]));
}

// Prefetch one K=32 chunk into stage at smem offset sb.
__device__ __forceinline__ void gemm_prefetch(uint32_t sb, int tid, int bm, int bn, int k0) {
#pragma unroll
    for (int p = 0; p < 2; ++p) {
        int idx = tid + p * 256;
        int row = idx >> 2, c16 = idx & 3;
        uint32_t off = (uint32_t)(row * 64 + c16 * 16);
        off ^= (uint32_t)(row & 3) << 4;
        cp16(sb + off,        g_Xh + (size_t)(bm + row) * DIN + k0 + c16 * 8);
        cp16(sb + 8192 + off, g_Xl + (size_t)(bm + row) * DIN + k0 + c16 * 8);
    }
    {
        int row = tid >> 3, c16 = tid & 7;
        uint32_t off = (uint32_t)(row * 128 + c16 * 16);
        off ^= (uint32_t)(row & 7) << 4;
        cp16(sb + 16384 + off, g_W1h + (size_t)(k0 + row) * DH + bn + c16 * 8);
        cp16(sb + 20480 + off, g_W1l + (size_t)(k0 + row) * DH + bn + c16 * 8);
    }
}

__global__ __launch_bounds__(256) void gemm1_mma_kernel() {
    extern __shared__ __align__(1024) char sm[];
    const uint32_t sbase = smem_u32(sm);
    const int tid = threadIdx.x;
    const int wid = tid >> 5, lane = tid & 31;
    const int bm = blockIdx.y * 128;
    const int bn = blockIdx.x * 64;
    const int wm0 = (wid & 3) * 32;
    const int wn0 = (wid >> 2) * 32;

    float d[2][4][4];
#pragma unroll
    for (int mt = 0; mt < 2; ++mt)
#pragma unroll
        for (int nt = 0; nt < 4; ++nt)
#pragma unroll
            for (int u = 0; u < 4; ++u) d[mt][nt][u] = 0.f;

    // prologue: stages 0..2 in flight
#pragma unroll
    for (int c = 0; c < NSTAGES - 1; ++c) {
        gemm_prefetch(sbase + (uint32_t)c * STAGE_BYTES, tid, bm, bn, c * CHUNK_K);
        asm volatile("cp.async.commit_group;");
    }

    for (int ch = 0; ch < NCHUNKS; ++ch) {
        asm volatile("cp.async.wait_group %0;" :: "n"(NSTAGES - 2));
        __syncthreads();
        const uint32_t stb = sbase + (uint32_t)(ch & (NSTAGES - 1)) * STAGE_BYTES;

#pragma unroll
        for (int ks = 0; ks < 2; ++ks) {
            const int kk = ks * 16;
            uint32_t ah[2][4], al[2][4], bh[4][2], bl[4][2];
#pragma unroll
            for (int mt = 0; mt < 2; ++mt) {
                int row = wm0 + mt * 16 + (lane & 15);
                uint32_t off = (uint32_t)(row * 64 + kk * 2 + ((lane >> 4) << 4));
                off ^= (uint32_t)(row & 3) << 4;
                ldmatrix_x4(ah[mt], stb + off);
                ldmatrix_x4(al[mt], stb + 8192 + off);
            }
#pragma unroll
            for (int nt = 0; nt < 4; ++nt) {
                int row = kk + (lane & 15);
                uint32_t off = (uint32_t)(row * 128 + (wn0 + nt * 8) * 2);
                off ^= (uint32_t)(row & 7) << 4;
                ldmatrix_x2t(bh[nt], stb + 16384 + off);
                ldmatrix_x2t(bl[nt], stb + 20480 + off);
            }
#pragma unroll
            for (int mt = 0; mt < 2; ++mt)
#pragma unroll
                for (int nt = 0; nt < 4; ++nt) {
                    mma_bf16(d[mt][nt], ah[mt], bh[nt]);
                    mma_bf16(d[mt][nt], ah[mt], bl[nt]);
                    mma_bf16(d[mt][nt], al[mt], bh[nt]);
                }
        }

        if (ch + NSTAGES - 1 < NCHUNKS) {
            gemm_prefetch(sbase + (uint32_t)((ch + NSTAGES - 1) & (NSTAGES - 1)) * STAGE_BYTES,
                          tid, bm, bn, (ch + NSTAGES - 1) * CHUNK_K);
        }
        asm volatile("cp.async.commit_group;");   // empty group at tail keeps FIFO uniform
    }

    // ---- epilogue: write Y1 as fp16 only ----
    const int group = lane >> 2, tig = lane & 3;
#pragma unroll
    for (int mt = 0; mt < 2; ++mt) {
#pragma unroll
        for (int nt = 0; nt < 4; ++nt) {
            int row = bm + wm0 + mt * 16 + group;
            int col = bn + wn0 + nt * 8 + tig * 2;
            __half2 h01 = __floats2half2_rn(d[mt][nt][0], d[mt][nt][1]);
            __half2 h23 = __floats2half2_rn(d[mt][nt][2], d[mt][nt][3]);
            *(__half2*)&g_Y1h[(size_t)row * DH + col] = h01;
            *(__half2*)&g_Y1h[(size_t)(row + 8) * DH + col] = h23;
        }
    }
}

// ------ fused prop1 + self-loop + bias + relu + @W2 (warp per dst node) ----
// lane owns columns [lane*8, lane*8+8) = one uint4 (8 halfs) per row.
__device__ __forceinline__ void acc8_fp16(uint4 v, float n, float4* a0, float4* a1) {
    float2 f0 = __half22float2(*(__half2*)&v.x);
    float2 f1 = __half22float2(*(__half2*)&v.y);
    float2 f2 = __half22float2(*(__half2*)&v.z);
    float2 f3 = __half22float2(*(__half2*)&v.w);
    a0->x = fmaf(n, f0.x, a0->x); a0->y = fmaf(n, f0.y, a0->y);
    a0->z = fmaf(n, f1.x, a0->z); a0->w = fmaf(n, f1.y, a0->w);
    a1->x = fmaf(n, f2.x, a1->x); a1->y = fmaf(n, f2.y, a1->y);
    a1->z = fmaf(n, f3.x, a1->z); a1->w = fmaf(n, f3.y, a1->w);
}

__global__ __launch_bounds__(256) void prop1node2_kernel(const float* __restrict__ b1,
                                                         const float* __restrict__ W2) {
    const int node = (blockIdx.x * blockDim.x + threadIdx.x) >> 5;
    const int lane = threadIdx.x & 31;
    if (node >= NNODES) return;
    const int e0 = node << CAPLG;
    const int cnt = g_cur[node];
    const float di = g_dinv[node];

    float4 a0 = make_float4(0.f, 0.f, 0.f, 0.f);
    float4 a1 = make_float4(0.f, 0.f, 0.f, 0.f);

    int e = 0;
    for (; e + 2 <= cnt; e += 2) {
        int sA = __ldg(&g_esrc[e0 + e]);
        int sB = __ldg(&g_esrc[e0 + e + 1]);
        float nA = __ldg(&g_dinv[sA]) * di;
        float nB = __ldg(&g_dinv[sB]) * di;
        uint4 vA = __ldg(&((const uint4*)(g_Y1h + (size_t)sA * DH))[lane]);
        uint4 vB = __ldg(&((const uint4*)(g_Y1h + (size_t)sB * DH))[lane]);
        acc8_fp16(vA, nA, &a0, &a1);
        acc8_fp16(vB, nB, &a0, &a1);
    }
    if (e < cnt) {
        int sA = __ldg(&g_esrc[e0 + e]);
        float nA = __ldg(&g_dinv[sA]) * di;
        uint4 vA = __ldg(&((const uint4*)(g_Y1h + (size_t)sA * DH))[lane]);
        acc8_fp16(vA, nA, &a0, &a1);
    }

    // self loop (fp16 Y1)
    {
        uint4 vS = __ldg(&((const uint4*)(g_Y1h + (size_t)node * DH))[lane]);
        acc8_fp16(vS, di * di, &a0, &a1);
    }

    const int fi = 2 * lane;
    float4 b0v = __ldg(&((const float4*)b1)[fi]);
    float4 b1v = __ldg(&((const float4*)b1)[fi + 1]);
    float h[8];
    h[0] = fmaxf(a0.x + b0v.x, 0.f); h[1] = fmaxf(a0.y + b0v.y, 0.f);
    h[2] = fmaxf(a0.z + b0v.z, 0.f); h[3] = fmaxf(a0.w + b0v.w, 0.f);
    h[4] = fmaxf(a1.x + b1v.x, 0.f); h[5] = fmaxf(a1.y + b1v.y, 0.f);
    h[6] = fmaxf(a1.z + b1v.z, 0.f); h[7] = fmaxf(a1.w + b1v.w, 0.f);
    float p0 = 0.f, p1 = 0.f;
#pragma unroll
    for (int j = 0; j < 8; ++j) {
        float2 w = __ldg(&((const float2*)W2)[lane * 8 + j]);
        p0 = fmaf(h[j], w.x, p0);
        p1 = fmaf(h[j], w.y, p1);
    }
#pragma unroll
    for (int off = 16; off > 0; off >>= 1) {
        p0 += __shfl_down_sync(0xffffffffu, p0, off);
        p1 += __shfl_down_sync(0xffffffffu, p1, off);
    }
    if (lane == 0) {
        g_Y2[node * 2 + 0] = p0;
        g_Y2[node * 2 + 1] = p1;
    }
}

// ---------------- fused prop2 + finalize (warp per dst node) ---------------
__global__ __launch_bounds__(256) void prop2fin_kernel(const float* __restrict__ b2,
                                                       float* __restrict__ out) {
    const int node = (blockIdx.x * blockDim.x + threadIdx.x) >> 5;
    const int lane = threadIdx.x & 31;
    if (node >= NNODES) return;
    const int e0 = node << CAPLG;
    const int cnt = g_cur[node];
    const float di = g_dinv[node];
    float sx = 0.f, sy = 0.f;
    for (int e = lane; e < cnt; e += 32) {
        int s = __ldg(&g_esrc[e0 + e]);
        float n = __ldg(&g_dinv[s]) * di;
        float2 y = __ldg(&((const float2*)g_Y2)[s]);
        sx = fmaf(n, y.x, sx);
        sy = fmaf(n, y.y, sy);
    }
#pragma unroll
    for (int off = 16; off > 0; off >>= 1) {
        sx += __shfl_down_sync(0xffffffffu, sx, off);
        sy += __shfl_down_sync(0xffffffffu, sy, off);
    }
    if (lane == 0) {
        float di2 = di * di;
        float2 y = __ldg(&((const float2*)g_Y2)[node]);
        float ex = sx + y.x * di2 + b2[0];
        float ey = sy + y.y * di2 + b2[1];
        g_ex[node] = ex;
        g_ey[node] = ey;
        out[2 * node + 0] = ex;
        out[2 * node + 1] = ey;
    }
}

// ---------------- q: symmetric upper-triangular 64x64 tiles ----------------
__device__ __forceinline__ float qval(float dx, float dy) {
    float d2 = fmaf(dx, dx, dy * dy);
    float pw = __powf(d2, BETA);
    float q  = __fdividef(1.0f, fmaf(ALPHA, pw, 1.0f));
    return d2 > 0.0f ? q : 1.0f;
}

__global__ __launch_bounds__(256) void q_kernel(float* __restrict__ qout) {
    __shared__ float qs[64][65];
    int b = blockIdx.x;
    int r = (int)((257.0f - sqrtf(66049.0f - 8.0f * (float)b)) * 0.5f);
    while ((r + 1) * 128 - ((r + 1) * r) / 2 <= b) ++r;
    while (r * 128 - (r * (r - 1)) / 2 > b) --r;
    int S = r * 128 - (r * (r - 1)) / 2;
    int bi = r;
    int bj = r + (b - S);
    int ty = threadIdx.x >> 4, tx = threadIdx.x & 15;
    int r0 = ty * 4, c0 = tx * 4;
    bool diag = (bi == bj);

    float4 xj = *(const float4*)&g_ex[bj * 64 + c0];
    float4 yj = *(const float4*)&g_ey[bj * 64 + c0];
#pragma unroll
    for (int u = 0; u < 4; ++u) {
        float xi = g_ex[bi * 64 + r0 + u];
        float yi = g_ey[bi * 64 + r0 + u];
        float4 v;
        v.x = qval(xi - xj.x, yi - yj.x);
        v.y = qval(xi - xj.y, yi - yj.y);
        v.z = qval(xi - xj.z, yi - yj.z);
        v.w = qval(xi - xj.w, yi - yj.w);
        __stcs((float4*)&qout[(size_t)(bi * 64 + r0 + u) * NNODES + bj * 64 + c0], v);
        if (!diag) {
            qs[r0 + u][c0 + 0] = v.x;
            qs[r0 + u][c0 + 1] = v.y;
            qs[r0 + u][c0 + 2] = v.z;
            qs[r0 + u][c0 + 3] = v.w;
        }
    }
    if (!diag) {
        __syncthreads();
#pragma unroll
        for (int u = 0; u < 4; ++u) {
            float4 v;
            v.x = qs[c0 + 0][r0 + u];
            v.y = qs[c0 + 1][r0 + u];
            v.z = qs[c0 + 2][r0 + u];
            v.w = qs[c0 + 3][r0 + u];
            __stcs((float4*)&qout[(size_t)(bj * 64 + r0 + u) * NNODES + bi * 64 + c0], v);
        }
    }
}

// ---------------------------------------------------------------------------
extern "C" void kernel_launch(void* const* d_in, const int* in_sizes, int n_in,
                              void* d_out, int out_size) {
    const float* X  = (const float*)d_in[0];
    const int*   ei = (const int*)  d_in[1];
    const float* W1 = (const float*)d_in[2];
    const float* b1 = (const float*)d_in[3];
    const float* W2 = (const float*)d_in[4];
    const float* b2 = (const float*)d_in[5];
    float* out = (float*)d_out;
    (void)in_sizes; (void)n_in; (void)out_size;

    const int* src = ei;
    const int* dst = ei + NEDGES;

    cudaFuncSetAttribute(gemm1_mma_kernel,
                         cudaFuncAttributeMaxDynamicSharedMemorySize, GEMM_SMEM);

    zero_small_kernel<<<NNODES / 256, 256>>>();
    scatter_kernel<<<NEDGES / 4 / 256, 256>>>(src, dst);
    dinv_kernel<<<NNODES / 256, 256>>>();
    split_kernel<<<NNODES * DIN / 8 / 256, 256>>>(X, W1);
    gemm1_mma_kernel<<<dim3(DH / 64, NNODES / 128), 256, GEMM_SMEM>>>();
    prop1node2_kernel<<<NNODES * 32 / 256, 256>>>(b1, W2);
    prop2fin_kernel<<<NNODES * 32 / 256, 256>>>(b2, out);
    q_kernel<<<128 * 129 / 2, 256>>>(out + NNODES * 2);
}

// round 13
// speedup vs baseline: 1.6947x; 1.0197x over previous
#include <cuda_runtime.h>
#include <cuda_fp16.h>
#include <cuda_bf16.h>
#include <cstdint>

#define NNODES 8192
#define NEDGES 262144
#define DIN    512
#define DH     256
#define ALPHA  0.1520f
#define BETA   0.7900f
#define CAPLG  7
#define CAP    128   // padded bin capacity per dst node (mean deg = 32, max ~60)

// ---------------- scratch (device globals; no allocation allowed) ----------
// INVARIANT: g_cur == 0 on entry to kernel_launch. Holds on the first call
// (device globals are zero-initialized at module load) and is re-established
// by prop2fin_kernel zeroing each node's counter after its final read.
__device__ int   g_cur [NNODES];         // in-degree after scatter
__device__ float g_dinv[NNODES];
__device__ int   g_esrc[NNODES * CAP];   // src index per slot
__device__ __nv_bfloat16 g_Xh [NNODES * DIN];
__device__ __nv_bfloat16 g_Xl [NNODES * DIN];
__device__ __nv_bfloat16 g_W1h[DIN * DH];
__device__ __nv_bfloat16 g_W1l[DIN * DH];
__device__ __half g_Y1h[NNODES * DH];   // X @ W1 (fp16, sole copy)
__device__ float g_Y2  [NNODES * 2];
__device__ float g_ex  [NNODES];
__device__ float g_ey  [NNODES];

// ---------------- scatter edges into padded bins (by dst); counts degree ---
__global__ void scatter_kernel(const int* __restrict__ src, const int* __restrict__ dst) {
    int t = blockIdx.x * blockDim.x + threadIdx.x;   // NEDGES/4 threads
#pragma unroll
    for (int j = 0; j < 4; ++j) {
        int e = t + j * (NEDGES / 4);
        int s = __ldg(&src[e]);
        int d = __ldg(&dst[e]);
        int pos = atomicAdd(&g_cur[d], 1);
        g_esrc[(d << CAPLG) + pos] = s;
    }
}

// ---------------- bf16 split pre-pass (X, W1) + dinv fused -----------------
// Thread i handles 8 consecutive floats -> one uint4 hi + one uint4 lo store.
__device__ __forceinline__ uint32_t pack_hi2(float a, float b) {
    __nv_bfloat16 h0 = __float2bfloat16_rn(a);
    __nv_bfloat16 h1 = __float2bfloat16_rn(b);
    return ((uint32_t)__bfloat16_as_ushort(h1) << 16) | __bfloat16_as_ushort(h0);
}
__device__ __forceinline__ uint32_t pack_lo2(float a, float b) {
    __nv_bfloat16 h0 = __float2bfloat16_rn(a);
    __nv_bfloat16 h1 = __float2bfloat16_rn(b);
    __nv_bfloat16 l0 = __float2bfloat16_rn(a - __bfloat162float(h0));
    __nv_bfloat16 l1 = __float2bfloat16_rn(b - __bfloat162float(h1));
    return ((uint32_t)__bfloat16_as_ushort(l1) << 16) | __bfloat16_as_ushort(l0);
}
__device__ __forceinline__ void split8(float4 v0, float4 v1, uint4* ph, uint4* pl) {
    ph->x = pack_hi2(v0.x, v0.y); ph->y = pack_hi2(v0.z, v0.w);
    ph->z = pack_hi2(v1.x, v1.y); ph->w = pack_hi2(v1.z, v1.w);
    pl->x = pack_lo2(v0.x, v0.y); pl->y = pack_lo2(v0.z, v0.w);
    pl->z = pack_lo2(v1.x, v1.y); pl->w = pack_lo2(v1.z, v1.w);
}

__global__ void split_kernel(const float* __restrict__ X, const float* __restrict__ W1) {
    int i = blockIdx.x * blockDim.x + threadIdx.x;   // NNODES*DIN/8 threads
    {
        float4 v0 = __ldg(&((const float4*)X)[2 * i]);
        float4 v1 = __ldg(&((const float4*)X)[2 * i + 1]);
        uint4 ph, pl;
        split8(v0, v1, &ph, &pl);
        ((uint4*)g_Xh)[i] = ph;
        ((uint4*)g_Xl)[i] = pl;
    }
    if (i < DIN * DH / 8) {
        float4 v0 = __ldg(&((const float4*)W1)[2 * i]);
        float4 v1 = __ldg(&((const float4*)W1)[2 * i + 1]);
        uint4 ph, pl;
        split8(v0, v1, &ph, &pl);
        ((uint4*)g_W1h)[i] = ph;
        ((uint4*)g_W1l)[i] = pl;
    }
    if (i < NNODES) {   // dinv (scatter has completed: sequential launches)
        g_dinv[i] = rsqrtf((float)g_cur[i] + 1.0f);
    }
}

// ================= GEMM1 via mma.sync bf16 (3-term split) ==================
// CTA tile 128(m) x 64(n); K in 16 chunks of 32; 4-stage cp.async pipeline.
#define CHUNK_K     32
#define NCHUNKS     (DIN / CHUNK_K)      // 16
#define STAGE_BYTES 24576
#define NSTAGES     4
#define GEMM_SMEM   (NSTAGES * STAGE_BYTES)

__device__ __forceinline__ uint32_t smem_u32(const void* p) {
    uint32_t a;
    asm("{ .reg .u64 t; cvta.to.shared.u64 t, %1; cvt.u32.u64 %0, t; }" : "=r"(a) : "l"(p));
    return a;
}
__device__ __forceinline__ void cp16(uint32_t dst, const void* src) {
    asm volatile("cp.async.cg.shared.global [%0], [%1], 16;" :: "r"(dst), "l"(src));
}
__device__ __forceinline__ void ldmatrix_x4(uint32_t* r, uint32_t addr) {
    asm volatile("ldmatrix.sync.aligned.m8n8.x4.shared.b16 {%0,%1,%2,%3}, [%4];"
                 : "=r"(r[0]), "=r"(r[1]), "=r"(r[2]), "=r"(r[3]) : "r"(addr));
}
__device__ __forceinline__ void ldmatrix_x2t(uint32_t* r, uint32_t addr) {
    asm volatile("ldmatrix.sync.aligned.m8n8.x2.trans.shared.b16 {%0,%1}, [%2];"
                 : "=r"(r[0]), "=r"(r[1]) : "r"(addr));
}
__device__ __forceinline__ void mma_bf16(float* d, const uint32_t* a, const uint32_t* b) {
    asm volatile(
        "mma.sync.aligned.m16n8k16.row.col.f32.bf16.bf16.f32 "
        "{%0,%1,%2,%3}, {%4,%5,%6,%7}, {%8,%9}, {%0,%1,%2,%3};"
        : "+f"(d[0]), "+f"(d[1]), "+f"(d[2]), "+f"(d[3])
        : "r"(a[0]), "r"(a[1]), "r"(a[2]), "r"(a[3]), "r"(b[0]), "r"(b[1]));
}

__device__ __forceinline__ void gemm_prefetch(uint32_t sb, int tid, int bm, int bn, int k0) {
#pragma unroll
    for (int p = 0; p < 2; ++p) {
        int idx = tid + p * 256;
        int row = idx >> 2, c16 = idx & 3;
        uint32_t off = (uint32_t)(row * 64 + c16 * 16);
        off ^= (uint32_t)(row & 3) << 4;
        cp16(sb + off,        g_Xh + (size_t)(bm + row) * DIN + k0 + c16 * 8);
        cp16(sb + 8192 + off, g_Xl + (size_t)(bm + row) * DIN + k0 + c16 * 8);
    }
    {
        int row = tid >> 3, c16 = tid & 7;
        uint32_t off = (uint32_t)(row * 128 + c16 * 16);
        off ^= (uint32_t)(row & 7) << 4;
        cp16(sb + 16384 + off, g_W1h + (size_t)(k0 + row) * DH + bn + c16 * 8);
        cp16(sb + 20480 + off, g_W1l + (size_t)(k0 + row) * DH + bn + c16 * 8);
    }
}

__global__ __launch_bounds__(256) void gemm1_mma_kernel() {
    extern __shared__ __align__(1024) char sm[];
    const uint32_t sbase = smem_u32(sm);
    const int tid = threadIdx.x;
    const int wid = tid >> 5, lane = tid & 31;
    const int bm = blockIdx.y * 128;
    const int bn = blockIdx.x * 64;
    const int wm0 = (wid & 3) * 32;
    const int wn0 = (wid >> 2) * 32;

    float d[2][4][4];
#pragma unroll
    for (int mt = 0; mt < 2; ++mt)
#pragma unroll
        for (int nt = 0; nt < 4; ++nt)
#pragma unroll
            for (int u = 0; u < 4; ++u) d[mt][nt][u] = 0.f;

#pragma unroll
    for (int c = 0; c < NSTAGES - 1; ++c) {
        gemm_prefetch(sbase + (uint32_t)c * STAGE_BYTES, tid, bm, bn, c * CHUNK_K);
        asm volatile("cp.async.commit_group;");
    }

    for (int ch = 0; ch < NCHUNKS; ++ch) {
        asm volatile("cp.async.wait_group %0;" :: "n"(NSTAGES - 2));
        __syncthreads();
        const uint32_t stb = sbase + (uint32_t)(ch & (NSTAGES - 1)) * STAGE_BYTES;

#pragma unroll
        for (int ks = 0; ks < 2; ++ks) {
            const int kk = ks * 16;
            uint32_t ah[2][4], al[2][4], bh[4][2], bl[4][2];
#pragma unroll
            for (int mt = 0; mt < 2; ++mt) {
                int row = wm0 + mt * 16 + (lane & 15);
                uint32_t off = (uint32_t)(row * 64 + kk * 2 + ((lane >> 4) << 4));
                off ^= (uint32_t)(row & 3) << 4;
                ldmatrix_x4(ah[mt], stb + off);
                ldmatrix_x4(al[mt], stb + 8192 + off);
            }
#pragma unroll
            for (int nt = 0; nt < 4; ++nt) {
                int row = kk + (lane & 15);
                uint32_t off = (uint32_t)(row * 128 + (wn0 + nt * 8) * 2);
                off ^= (uint32_t)(row & 7) << 4;
                ldmatrix_x2t(bh[nt], stb + 16384 + off);
                ldmatrix_x2t(bl[nt], stb + 20480 + off);
            }
#pragma unroll
            for (int mt = 0; mt < 2; ++mt)
#pragma unroll
                for (int nt = 0; nt < 4; ++nt) {
                    mma_bf16(d[mt][nt], ah[mt], bh[nt]);
                    mma_bf16(d[mt][nt], ah[mt], bl[nt]);
                    mma_bf16(d[mt][nt], al[mt], bh[nt]);
                }
        }

        if (ch + NSTAGES - 1 < NCHUNKS) {
            gemm_prefetch(sbase + (uint32_t)((ch + NSTAGES - 1) & (NSTAGES - 1)) * STAGE_BYTES,
                          tid, bm, bn, (ch + NSTAGES - 1) * CHUNK_K);
        }
        asm volatile("cp.async.commit_group;");
    }

    // ---- epilogue: write Y1 as fp16 only ----
    const int group = lane >> 2, tig = lane & 3;
#pragma unroll
    for (int mt = 0; mt < 2; ++mt) {
#pragma unroll
        for (int nt = 0; nt < 4; ++nt) {
            int row = bm + wm0 + mt * 16 + group;
            int col = bn + wn0 + nt * 8 + tig * 2;
            __half2 h01 = __floats2half2_rn(d[mt][nt][0], d[mt][nt][1]);
            __half2 h23 = __floats2half2_rn(d[mt][nt][2], d[mt][nt][3]);
            *(__half2*)&g_Y1h[(size_t)row * DH + col] = h01;
            *(__half2*)&g_Y1h[(size_t)(row + 8) * DH + col] = h23;
        }
    }
}

// ------ fused prop1 + self-loop + bias + relu + @W2 (warp per dst node) ----
__device__ __forceinline__ void acc8_fp16(uint4 v, float n, float4* a0, float4* a1) {
    float2 f0 = __half22float2(*(__half2*)&v.x);
    float2 f1 = __half22float2(*(__half2*)&v.y);
    float2 f2 = __half22float2(*(__half2*)&v.z);
    float2 f3 = __half22float2(*(__half2*)&v.w);
    a0->x = fmaf(n, f0.x, a0->x); a0->y = fmaf(n, f0.y, a0->y);
    a0->z = fmaf(n, f1.x, a0->z); a0->w = fmaf(n, f1.y, a0->w);
    a1->x = fmaf(n, f2.x, a1->x); a1->y = fmaf(n, f2.y, a1->y);
    a1->z = fmaf(n, f3.x, a1->z); a1->w = fmaf(n, f3.y, a1->w);
}

__global__ __launch_bounds__(256) void prop1node2_kernel(const float* __restrict__ b1,
                                                         const float* __restrict__ W2) {
    const int node = (blockIdx.x * blockDim.x + threadIdx.x) >> 5;
    const int lane = threadIdx.x & 31;
    if (node >= NNODES) return;
    const int e0 = node << CAPLG;
    const int cnt = g_cur[node];
    const float di = g_dinv[node];

    float4 a0 = make_float4(0.f, 0.f, 0.f, 0.f);
    float4 a1 = make_float4(0.f, 0.f, 0.f, 0.f);

    int e = 0;
    for (; e + 2 <= cnt; e += 2) {
        int sA = __ldg(&g_esrc[e0 + e]);
        int sB = __ldg(&g_esrc[e0 + e + 1]);
        float nA = __ldg(&g_dinv[sA]) * di;
        float nB = __ldg(&g_dinv[sB]) * di;
        uint4 vA = __ldg(&((const uint4*)(g_Y1h + (size_t)sA * DH))[lane]);
        uint4 vB = __ldg(&((const uint4*)(g_Y1h + (size_t)sB * DH))[lane]);
        acc8_fp16(vA, nA, &a0, &a1);
        acc8_fp16(vB, nB, &a0, &a1);
    }
    if (e < cnt) {
        int sA = __ldg(&g_esrc[e0 + e]);
        float nA = __ldg(&g_dinv[sA]) * di;
        uint4 vA = __ldg(&((const uint4*)(g_Y1h + (size_t)sA * DH))[lane]);
        acc8_fp16(vA, nA, &a0, &a1);
    }

    {   // self loop
        uint4 vS = __ldg(&((const uint4*)(g_Y1h + (size_t)node * DH))[lane]);
        acc8_fp16(vS, di * di, &a0, &a1);
    }

    const int fi = 2 * lane;
    float4 b0v = __ldg(&((const float4*)b1)[fi]);
    float4 b1v = __ldg(&((const float4*)b1)[fi + 1]);
    float h[8];
    h[0] = fmaxf(a0.x + b0v.x, 0.f); h[1] = fmaxf(a0.y + b0v.y, 0.f);
    h[2] = fmaxf(a0.z + b0v.z, 0.f); h[3] = fmaxf(a0.w + b0v.w, 0.f);
    h[4] = fmaxf(a1.x + b1v.x, 0.f); h[5] = fmaxf(a1.y + b1v.y, 0.f);
    h[6] = fmaxf(a1.z + b1v.z, 0.f); h[7] = fmaxf(a1.w + b1v.w, 0.f);
    float p0 = 0.f, p1 = 0.f;
#pragma unroll
    for (int j = 0; j < 8; ++j) {
        float2 w = __ldg(&((const float2*)W2)[lane * 8 + j]);
        p0 = fmaf(h[j], w.x, p0);
        p1 = fmaf(h[j], w.y, p1);
    }
#pragma unroll
    for (int off = 16; off > 0; off >>= 1) {
        p0 += __shfl_down_sync(0xffffffffu, p0, off);
        p1 += __shfl_down_sync(0xffffffffu, p1, off);
    }
    if (lane == 0) {
        g_Y2[node * 2 + 0] = p0;
        g_Y2[node * 2 + 1] = p1;
    }
}

// ------ fused prop2 + finalize (warp per dst node); re-zeroes g_cur --------
__global__ __launch_bounds__(256) void prop2fin_kernel(const float* __restrict__ b2,
                                                       float* __restrict__ out) {
    const int node = (blockIdx.x * blockDim.x + threadIdx.x) >> 5;
    const int lane = threadIdx.x & 31;
    if (node >= NNODES) return;
    const int e0 = node << CAPLG;
    const int cnt = g_cur[node];
    const float di = g_dinv[node];
    float sx = 0.f, sy = 0.f;
    for (int e = lane; e < cnt; e += 32) {
        int s = __ldg(&g_esrc[e0 + e]);
        float n = __ldg(&g_dinv[s]) * di;
        float2 y = __ldg(&((const float2*)g_Y2)[s]);
        sx = fmaf(n, y.x, sx);
        sy = fmaf(n, y.y, sy);
    }
#pragma unroll
    for (int off = 16; off > 0; off >>= 1) {
        sx += __shfl_down_sync(0xffffffffu, sx, off);
        sy += __shfl_down_sync(0xffffffffu, sy, off);
    }
    if (lane == 0) {
        float di2 = di * di;
        float2 y = __ldg(&((const float2*)g_Y2)[node]);
        float ex = sx + y.x * di2 + b2[0];
        float ey = sy + y.y * di2 + b2[1];
        g_ex[node] = ex;
        g_ey[node] = ey;
        out[2 * node + 0] = ex;
        out[2 * node + 1] = ey;
        g_cur[node] = 0;   // restore the g_cur == 0 invariant for next replay
    }
}

// ---------------- q: symmetric upper-triangular 64x64 tiles ----------------
__device__ __forceinline__ float qval(float dx, float dy) {
    float d2 = fmaf(dx, dx, dy * dy);
    float pw = __powf(d2, BETA);
    float q  = __fdividef(1.0f, fmaf(ALPHA, pw, 1.0f));
    return d2 > 0.0f ? q : 1.0f;
}

__global__ __launch_bounds__(256) void q_kernel(float* __restrict__ qout) {
    __shared__ float qs[64][65];
    int b = blockIdx.x;
    int r = (int)((257.0f - sqrtf(66049.0f - 8.0f * (float)b)) * 0.5f);
    while ((r + 1) * 128 - ((r + 1) * r) / 2 <= b) ++r;
    while (r * 128 - (r * (r - 1)) / 2 > b) --r;
    int S = r * 128 - (r * (r - 1)) / 2;
    int bi = r;
    int bj = r + (b - S);
    int ty = threadIdx.x >> 4, tx = threadIdx.x & 15;
    int r0 = ty * 4, c0 = tx * 4;
    bool diag = (bi == bj);

    float4 xj = *(const float4*)&g_ex[bj * 64 + c0];
    float4 yj = *(const float4*)&g_ey[bj * 64 + c0];
#pragma unroll
    for (int u = 0; u < 4; ++u) {
        float xi = g_ex[bi * 64 + r0 + u];
        float yi = g_ey[bi * 64 + r0 + u];
        float4 v;
        v.x = qval(xi - xj.x, yi - yj.x);
        v.y = qval(xi - xj.y, yi - yj.y);
        v.z = qval(xi - xj.z, yi - yj.z);
        v.w = qval(xi - xj.w, yi - yj.w);
        __stcs((float4*)&qout[(size_t)(bi * 64 + r0 + u) * NNODES + bj * 64 + c0], v);
        if (!diag) {
            qs[r0 + u][c0 + 0] = v.x;
            qs[r0 + u][c0 + 1] = v.y;
            qs[r0 + u][c0 + 2] = v.z;
            qs[r0 + u][c0 + 3] = v.w;
        }
    }
    if (!diag) {
        __syncthreads();
#pragma unroll
        for (int u = 0; u < 4; ++u) {
            float4 v;
            v.x = qs[c0 + 0][r0 + u];
            v.y = qs[c0 + 1][r0 + u];
            v.z = qs[c0 + 2][r0 + u];
            v.w = qs[c0 + 3][r0 + u];
            __stcs((float4*)&qout[(size_t)(bj * 64 + r0 + u) * NNODES + bi * 64 + c0], v);
        }
    }
}

// ---------------------------------------------------------------------------
extern "C" void kernel_launch(void* const* d_in, const int* in_sizes, int n_in,
                              void* d_out, int out_size) {
    const float* X  = (const float*)d_in[0];
    const int*   ei = (const int*)  d_in[1];
    const float* W1 = (const float*)d_in[2];
    const float* b1 = (const float*)d_in[3];
    const float* W2 = (const float*)d_in[4];
    const float* b2 = (const float*)d_in[5];
    float* out = (float*)d_out;
    (void)in_sizes; (void)n_in; (void)out_size;

    const int* src = ei;
    const int* dst = ei + NEDGES;

    cudaFuncSetAttribute(gemm1_mma_kernel,
                         cudaFuncAttributeMaxDynamicSharedMemorySize, GEMM_SMEM);

    scatter_kernel<<<NEDGES / 4 / 256, 256>>>(src, dst);
    split_kernel<<<NNODES * DIN / 8 / 256, 256>>>(X, W1);   // + dinv fused
    gemm1_mma_kernel<<<dim3(DH / 64, NNODES / 128), 256, GEMM_SMEM>>>();
    prop1node2_kernel<<<NNODES * 32 / 256, 256>>>(b1, W2);
    prop2fin_kernel<<<NNODES * 32 / 256, 256>>>(b2, out);   // re-zeroes g_cur
    q_kernel<<<128 * 129 / 2, 256>>>(out + NNODES * 2);
}